// round 4
// baseline (speedup 1.0000x reference)
#include <cuda_runtime.h>

#define HIDDEN   256
#define LATENT   128
#define VOCAB    32000
#define MAXLEN   64
#define MAXSTEPS 128
#define NNODES   511
#define NB       148
#define NT       256
#define NWARP    (NT/32)
#define NWORK    (NB - 16)        // 132 worker CTAs (16..147)

// ---------------- device scratch (no allocation allowed) ----------------
__device__ __align__(16) float g_h[NNODES * HIDDEN];      // encoder hidden states
__device__ __align__(16) float g_stack[MAXLEN * LATENT];  // decoder stack (CTA 0 only)
__device__ __align__(16) float g_dco[MAXSTEPS + 1][HIDDEN]; // published co deck
__device__ int g_dflag[MAXSTEPS + 1];                     // step flag; -1 = sentinel
__device__ int g_dop[MAXSTEPS + 1];                       // step output row
// monotonic counters (NEVER reset; survive graph replays)
__device__ volatile unsigned g_enc;   // subtree-done count
__device__ volatile unsigned g_z;     // zeroing-done count
__device__ volatile unsigned g_pubv;  // published step count
// entry barrier (sense-reversal, survives replays)
__device__ __align__(128) unsigned g_cnt = 0;
__device__ __align__(128) volatile unsigned g_gen = 0;

__device__ __forceinline__ void grid_sync() {
    __threadfence();
    __syncthreads();
    if (threadIdx.x == 0) {
        unsigned gen = g_gen;
        if (atomicAdd(&g_cnt, 1u) == NB - 1u) {
            g_cnt = 0;
            __threadfence();
            g_gen = gen + 1u;
        } else {
            while (g_gen == gen) { }
        }
        __threadfence();
    }
    __syncthreads();
}

// warp dot: 256-float row vs lane-resident x, streaming (L2)
__device__ __forceinline__ float wdot256c(const float* __restrict__ row,
                                          float4 c0, float4 c1, int lane) {
    const float4* r4 = reinterpret_cast<const float4*>(row);
    float4 a = __ldcg(r4 + lane);
    float4 b = __ldcg(r4 + 32 + lane);
    float s = a.x * c0.x + a.y * c0.y + a.z * c0.z + a.w * c0.w;
    s      += b.x * c1.x + b.y * c1.y + b.z * c1.z + b.w * c1.w;
#pragma unroll
    for (int o = 16; o; o >>= 1) s += __shfl_xor_sync(0xffffffffu, s, o);
    return s;
}
// L1-cached variant (small reused weights)
__device__ __forceinline__ float wdot256g(const float* __restrict__ row,
                                          float4 c0, float4 c1, int lane) {
    const float4* r4 = reinterpret_cast<const float4*>(row);
    float4 a = __ldg(r4 + lane);
    float4 b = __ldg(r4 + 32 + lane);
    float s = a.x * c0.x + a.y * c0.y + a.z * c0.z + a.w * c0.w;
    s      += b.x * c1.x + b.y * c1.y + b.z * c1.z + b.w * c1.w;
#pragma unroll
    for (int o = 16; o; o >>= 1) s += __shfl_xor_sync(0xffffffffu, s, o);
    return s;
}

// gather cat rows [emb(node); h(2n+1); h(2n+2)] for nb nodes into shared
__device__ __forceinline__ void enc_gather(const float* __restrict__ embed,
                                           const int* __restrict__ values,
                                           int n0, int nb, bool leaves,
                                           float4* sh4, int tid) {
    for (int idx = tid; idx < nb * 192; idx += NT) {
        int m  = idx / 192;
        int k4 = idx - m * 192;
        int node = n0 + m;
        const float4* src;
        if (k4 < 64) {
            src = reinterpret_cast<const float4*>(embed + (size_t)values[node] * HIDDEN) + k4;
        } else if (k4 < 128) {
            int c = 2 * node + 1;
            src = leaves
                ? reinterpret_cast<const float4*>(embed + (size_t)values[c] * HIDDEN) + (k4 - 64)
                : reinterpret_cast<const float4*>(g_h + (size_t)c * HIDDEN) + (k4 - 64);
        } else {
            int c = 2 * node + 2;
            src = leaves
                ? reinterpret_cast<const float4*>(embed + (size_t)values[c] * HIDDEN) + (k4 - 128)
                : reinterpret_cast<const float4*>(g_h + (size_t)c * HIDDEN) + (k4 - 128);
        }
        sh4[idx] = *src;
    }
}

// batched 768->256 matvec (up to 8 nodes), register-resident accumulators
__device__ __forceinline__ void enc_matvec(const float* __restrict__ Wpar,
                                           const float* __restrict__ bpar,
                                           const float4* sh4, int n0, int nb,
                                           int lane, int warp) {
    for (int r = warp; r < HIDDEN; r += NWARP) {
        const float4* w4 = reinterpret_cast<const float4*>(Wpar + (size_t)r * 768);
        float acc[8];
#pragma unroll
        for (int m = 0; m < 8; ++m) acc[m] = 0.f;
#pragma unroll
        for (int j = 0; j < 6; ++j) {
            float4 w = __ldg(w4 + j * 32 + lane);
#pragma unroll
            for (int m = 0; m < 8; ++m) {
                float4 x = sh4[m * 192 + j * 32 + lane];
                acc[m] += w.x * x.x + w.y * x.y + w.z * x.z + w.w * x.w;
            }
        }
        float bb = __ldg(bpar + r);
#pragma unroll
        for (int m = 0; m < 8; ++m) {
            float s = acc[m];
#pragma unroll
            for (int o = 16; o; o >>= 1) s += __shfl_xor_sync(0xffffffffu, s, o);
            if (lane == 0 && m < nb) g_h[(size_t)(n0 + m) * HIDDEN + r] = s + bb;
        }
    }
}

__global__ void __launch_bounds__(NT, 1) vae_kernel(
    const float* __restrict__ embed, const float* __restrict__ Wpar, const float* __restrict__ bpar,
    const float* __restrict__ Wmu,   const float* __restrict__ bmu,
    const float* __restrict__ Wlv,   const float* __restrict__ blv,
    const float* __restrict__ W1,    const float* __restrict__ b1,
    const float* __restrict__ W2,    const float* __restrict__ b2,
    const float* __restrict__ Wl,    const float* __restrict__ bl,
    const float* __restrict__ Wp,    const float* __restrict__ bp,
    const float* __restrict__ eps,   const int* __restrict__ values,
    float* __restrict__ out, int n_out)
{
    const int tid  = threadIdx.x;
    const int lane = tid & 31;
    const int warp = tid >> 5;
    const int cta  = blockIdx.x;

    __shared__ float4 sh4[8 * 192];        // 24 KB encoder cat buffers
    __shared__ float s_mu[LATENT], s_lv[LATENT];
    __shared__ float s_hm[HIDDEN];
    __shared__ float s_node[LATENT];
    __shared__ float s_co[HIDDEN];
    __shared__ int   sh_flag, sh_op;

    // snapshot monotonic baselines (stable: no one increments until after barrier)
    const unsigned base_enc = g_enc;
    const unsigned base_z   = g_z;
    const unsigned base_pub = g_pubv;
    grid_sync();   // single launch-wide rendezvous (all CTAs fresh => cheap)

    if (cta >= 16) {
        // ================= WORKERS =================
        // zero the poisoned out buffer
        float4 z4 = make_float4(0.f, 0.f, 0.f, 0.f);
        float4* o4 = reinterpret_cast<float4*>(out);
        int n4 = n_out >> 2;
        for (int i = (cta - 16) * NT + tid; i < n4; i += NWORK * NT) o4[i] = z4;
        if (cta == 16) for (int i = (n4 << 2) + tid; i < n_out; i += NT) out[i] = 0.f;
        __threadfence();
        __syncthreads();
        if (tid == 0) {
            atomicAdd((unsigned*)&g_z, 1u);
            while (g_z - base_z < (unsigned)NWORK) { }   // all zeroing done
        }
        __syncthreads();

        // consume published decoder steps
        for (int s = 0; ; ++s) {
            if (tid == 0) {
                while ((int)(g_pubv - base_pub) <= s) { }
                __threadfence();
                sh_flag = g_dflag[s];
                sh_op   = g_dop[s];
            }
            __syncthreads();
            const int flag = sh_flag;
            if (flag < 0) break;                      // sentinel
            const int op = sh_op;

            const float4* cb = reinterpret_cast<const float4*>(g_dco[s]);
            const float4 c0 = __ldcg(cb + lane);
            const float4 c1 = __ldcg(cb + 32 + lane);

            const float* W    = flag ? Wp : Wl;
            const float* bias = flag ? bp : bl;
            float* orow = out + (size_t)op * VOCAB;
            const int gw     = (cta - 16) * NWARP + warp;
            const int stride = NWORK * NWARP * 4;
            for (int r = gw * 4; r < VOCAB; r += stride) {
                float s0 = wdot256c(W + (size_t)(r + 0) * HIDDEN, c0, c1, lane);
                float s1 = wdot256c(W + (size_t)(r + 1) * HIDDEN, c0, c1, lane);
                float s2 = wdot256c(W + (size_t)(r + 2) * HIDDEN, c0, c1, lane);
                float s3 = wdot256c(W + (size_t)(r + 3) * HIDDEN, c0, c1, lane);
                if (lane == 0) {
                    orow[r + 0] = s0 + bias[r + 0];
                    orow[r + 1] = s1 + bias[r + 1];
                    orow[r + 2] = s2 + bias[r + 2];
                    orow[r + 3] = s3 + bias[r + 3];
                }
            }
            __syncthreads();   // keep sh_flag/sh_op stable for stragglers
        }
        return;
    }

    // ================= ENCODER: 16 independent level-4 subtrees =================
    {
        const int r = 15 + cta;                 // subtree root at level 4
        int n0 = ((r + 1) << 3) - 1;            // 8 level-7 nodes (leaf children)
        enc_gather(embed, values, n0, 8, true, sh4, tid);
        __syncthreads();
        enc_matvec(Wpar, bpar, sh4, n0, 8, lane, warp);
        __syncthreads();
        n0 = ((r + 1) << 2) - 1;                // 4 level-6 nodes
        enc_gather(embed, values, n0, 4, false, sh4, tid);
        __syncthreads();
        enc_matvec(Wpar, bpar, sh4, n0, 4, lane, warp);
        __syncthreads();
        n0 = ((r + 1) << 1) - 1;                // 2 level-5 nodes
        enc_gather(embed, values, n0, 2, false, sh4, tid);
        __syncthreads();
        enc_matvec(Wpar, bpar, sh4, n0, 2, lane, warp);
        __syncthreads();
        enc_gather(embed, values, r, 1, false, sh4, tid);   // the level-4 root
        __syncthreads();
        enc_matvec(Wpar, bpar, sh4, r, 1, lane, warp);
    }
    if (cta != 0) {        // subtree CTAs 1..15 signal and exit
        __threadfence();
        __syncthreads();
        if (tid == 0) atomicAdd((unsigned*)&g_enc, 1u);
        return;
    }

    // ================= CTA 0: levels 3..0 + latent + sequential decoder =================
    __syncthreads();
    if (tid == 0) {
        while (g_enc - base_enc < 15u) { }   // wait for peer subtrees
        __threadfence();
    }
    __syncthreads();
#pragma unroll
    for (int lvl = 3; lvl >= 0; --lvl) {
        int base = (1 << lvl) - 1, cnt = 1 << lvl;
        enc_gather(embed, values, base, cnt, false, sh4, tid);
        __syncthreads();
        enc_matvec(Wpar, bpar, sh4, base, cnt, lane, warp);
        __syncthreads();
    }

    // wait for workers' zeroing before touching the out tail
    if (tid == 0) { while (g_z - base_z < (unsigned)NWORK) { } __threadfence(); }
    __syncthreads();

    // mu / logvar from root
    {
        float4 r0 = reinterpret_cast<const float4*>(g_h)[lane];
        float4 r1 = reinterpret_cast<const float4*>(g_h)[32 + lane];
        for (int rr = warp; rr < 2 * LATENT; rr += NWARP) {
            const float* Wr = (rr < LATENT) ? Wmu + (size_t)rr * HIDDEN
                                            : Wlv + (size_t)(rr - LATENT) * HIDDEN;
            float s = wdot256g(Wr, r0, r1, lane);
            if (lane == 0) {
                float v = s + ((rr < LATENT) ? bmu[rr] : blv[rr - LATENT]);
                if (rr < LATENT) s_mu[rr] = v; else s_lv[rr - LATENT] = v;
                out[(size_t)MAXSTEPS * VOCAB + rr] = v;
            }
        }
    }
    __syncthreads();
    if (tid < LATENT) {
        float z = s_mu[tid] + eps[tid] * expf(0.5f * s_lv[tid]);
        s_node[tid] = z;
        g_stack[tid] = z;
    }
    __syncthreads();

    // ---- sequential decoder chain; publish each step to the deck ----
    int sp = 1, op = 0, flag;
    {   // phase A for step 0: hmid = leaky(W1@z), co = W2@hmid
        float4 zc = reinterpret_cast<const float4*>(s_node)[lane];
        for (int rr = warp; rr < HIDDEN; rr += NWARP) {
            float4 a = __ldg(reinterpret_cast<const float4*>(W1 + (size_t)rr * LATENT) + lane);
            float s = a.x * zc.x + a.y * zc.y + a.z * zc.z + a.w * zc.w;
#pragma unroll
            for (int o = 16; o; o >>= 1) s += __shfl_xor_sync(0xffffffffu, s, o);
            if (lane == 0) { s += b1[rr]; s_hm[rr] = s > 0.f ? s : 0.2f * s; }
        }
        __syncthreads();
        float4 h0 = reinterpret_cast<const float4*>(s_hm)[lane];
        float4 h1 = reinterpret_cast<const float4*>(s_hm)[32 + lane];
        for (int rr = warp; rr < HIDDEN + 1; rr += NWARP) {
            float s = wdot256g(W2 + (size_t)rr * HIDDEN, h0, h1, lane);
            if (lane == 0) {
                s += b2[rr];
                if (rr == 0) sh_flag = (s > 0.f) ? 1 : 0;  // sp-1=0 <= 62 always
                else         s_co[rr - 1] = s;
            }
        }
        __syncthreads();
        flag = sh_flag;
    }

    int it = 0;
    while (true) {
        // publish step `it`
        for (int i = tid; i < HIDDEN; i += NT) g_dco[it][i] = s_co[i];
        if (tid == 0) { g_dflag[it] = flag; g_dop[it] = op; }
        __threadfence();
        __syncthreads();
        if (tid == 0) g_pubv = base_pub + (unsigned)(it + 1);

        // next-state compute (stack + next node)
        int sp_next;
        if (flag) {
            const float4* cb = reinterpret_cast<const float4*>(s_co);
            float4 c0 = cb[lane], c1 = cb[32 + lane];
            for (int j = warp; j < 2 * LATENT; j += NWARP) {
                float s = wdot256c(Wp + (size_t)(VOCAB + j) * HIDDEN, c0, c1, lane);
                if (lane == 0) {
                    float v = s + bp[VOCAB + j];
                    if (j < LATENT) {
                        g_stack[(sp - 1) * LATENT + j] = v;     // ll
                    } else {
                        g_stack[sp * LATENT + (j - LATENT)] = v; // rl
                        s_node[j - LATENT] = v;                  // next node = rl
                    }
                }
            }
            sp_next = sp + 1;
        } else {
            sp_next = sp - 1;
            if (tid < LATENT && sp_next > 0) s_node[tid] = g_stack[(sp_next - 1) * LATENT + tid];
        }
        __syncthreads();

        ++it;
        if (sp_next <= 0 || it >= MAXSTEPS) {   // inactive (or steps exhausted): sentinel
            if (tid == 0) g_dflag[it] = -1;
            __threadfence();
            __syncthreads();
            if (tid == 0) g_pubv = base_pub + (unsigned)(it + 1);
            break;
        }

        // phase A for next step
        {
            float4 zc = reinterpret_cast<const float4*>(s_node)[lane];
            for (int rr = warp; rr < HIDDEN; rr += NWARP) {
                float4 a = __ldg(reinterpret_cast<const float4*>(W1 + (size_t)rr * LATENT) + lane);
                float s = a.x * zc.x + a.y * zc.y + a.z * zc.z + a.w * zc.w;
#pragma unroll
                for (int o = 16; o; o >>= 1) s += __shfl_xor_sync(0xffffffffu, s, o);
                if (lane == 0) { s += b1[rr]; s_hm[rr] = s > 0.f ? s : 0.2f * s; }
            }
            __syncthreads();
            float4 h0 = reinterpret_cast<const float4*>(s_hm)[lane];
            float4 h1 = reinterpret_cast<const float4*>(s_hm)[32 + lane];
            for (int rr = warp; rr < HIDDEN + 1; rr += NWARP) {
                float s = wdot256g(W2 + (size_t)rr * HIDDEN, h0, h1, lane);
                if (lane == 0) {
                    s += b2[rr];
                    if (rr == 0) sh_flag = (s > 0.f && sp_next <= MAXLEN - 1) ? 1 : 0;
                    else         s_co[rr - 1] = s;
                }
            }
            __syncthreads();
            flag = sh_flag;
        }
        op += 1;
        sp = sp_next;
    }
}

extern "C" void kernel_launch(void* const* d_in, const int* in_sizes, int n_in,
                              void* d_out, int out_size) {
    const float* embed = (const float*)d_in[0];
    const float* Wpar  = (const float*)d_in[1];
    const float* bpar  = (const float*)d_in[2];
    const float* Wmu   = (const float*)d_in[3];
    const float* bmu   = (const float*)d_in[4];
    const float* Wlv   = (const float*)d_in[5];
    const float* blv   = (const float*)d_in[6];
    const float* W1    = (const float*)d_in[7];
    const float* b1    = (const float*)d_in[8];
    const float* W2    = (const float*)d_in[9];
    const float* b2    = (const float*)d_in[10];
    const float* Wl    = (const float*)d_in[11];
    const float* bl    = (const float*)d_in[12];
    const float* Wp    = (const float*)d_in[13];
    const float* bp    = (const float*)d_in[14];
    const float* eps   = (const float*)d_in[15];
    const int*   values= (const int*)  d_in[16];
    // d_in[17]=left, d_in[18]=right: fixed complete-tree topology; unused.

    vae_kernel<<<NB, NT>>>(embed, Wpar, bpar, Wmu, bmu, Wlv, blv,
                           W1, b1, W2, b2, Wl, bl, Wp, bp, eps, values,
                           (float*)d_out, out_size);
}

// round 5
// speedup vs baseline: 2.7980x; 2.7980x over previous
#include <cuda_runtime.h>

#define HIDDEN   256
#define LATENT   128
#define VOCAB    32000
#define MAXLEN   64
#define MAXSTEPS 128
#define NNODES   511
#define NB       148
#define NT       256
#define NWARP    (NT/32)
#define NCONS    (NB - 1)          // 147 consumer/zeroer CTAs

// ---------------- device scratch (no allocation allowed) ----------------
__device__ __align__(16) float g_h[255 * HIDDEN];          // internal-node hidden states
__device__ __align__(16) float g_stack[MAXLEN * LATENT];   // decoder stack (CTA 0 only)
__device__ __align__(16) float g_dco[MAXSTEPS + 1][HIDDEN];// published co deck
__device__ int g_dflag[MAXSTEPS + 1];                      // step flag; -1 = sentinel
__device__ int g_dop[MAXSTEPS + 1];                        // step output row
__device__ volatile unsigned g_nf[255];                    // node done-flags (epoch-tagged)
// monotonic counters (never reset; survive graph replays)
__device__ volatile unsigned g_z;     // zeroing-done count
__device__ volatile unsigned g_pubv;  // published step count
// entry barrier (sense-reversal; g_gen doubles as the per-launch epoch)
__device__ __align__(128) unsigned g_cnt = 0;
__device__ __align__(128) volatile unsigned g_gen = 0;

__device__ __forceinline__ void grid_sync() {
    __threadfence();
    __syncthreads();
    if (threadIdx.x == 0) {
        unsigned gen = g_gen;
        if (atomicAdd(&g_cnt, 1u) == NB - 1u) {
            g_cnt = 0;
            __threadfence();
            g_gen = gen + 1u;
        } else {
            while (g_gen == gen) { }
        }
        __threadfence();
    }
    __syncthreads();
}

// warp dot: 256-float row vs lane-resident x, streaming (L2)
__device__ __forceinline__ float wdot256c(const float* __restrict__ row,
                                          float4 c0, float4 c1, int lane) {
    const float4* r4 = reinterpret_cast<const float4*>(row);
    float4 a = __ldcg(r4 + lane);
    float4 b = __ldcg(r4 + 32 + lane);
    float s = a.x * c0.x + a.y * c0.y + a.z * c0.z + a.w * c0.w;
    s      += b.x * c1.x + b.y * c1.y + b.z * c1.z + b.w * c1.w;
#pragma unroll
    for (int o = 16; o; o >>= 1) s += __shfl_xor_sync(0xffffffffu, s, o);
    return s;
}
// L1-cached variant (small reused weights)
__device__ __forceinline__ float wdot256g(const float* __restrict__ row,
                                          float4 c0, float4 c1, int lane) {
    const float4* r4 = reinterpret_cast<const float4*>(row);
    float4 a = __ldg(r4 + lane);
    float4 b = __ldg(r4 + 32 + lane);
    float s = a.x * c0.x + a.y * c0.y + a.z * c0.z + a.w * c0.w;
    s      += b.x * c1.x + b.y * c1.y + b.z * c1.z + b.w * c1.w;
#pragma unroll
    for (int o = 16; o; o >>= 1) s += __shfl_xor_sync(0xffffffffu, s, o);
    return s;
}

__global__ void __launch_bounds__(NT, 1) vae_kernel(
    const float* __restrict__ embed, const float* __restrict__ Wpar, const float* __restrict__ bpar,
    const float* __restrict__ Wmu,   const float* __restrict__ bmu,
    const float* __restrict__ Wlv,   const float* __restrict__ blv,
    const float* __restrict__ W1,    const float* __restrict__ b1,
    const float* __restrict__ W2,    const float* __restrict__ b2,
    const float* __restrict__ Wl,    const float* __restrict__ bl,
    const float* __restrict__ Wp,    const float* __restrict__ bp,
    const float* __restrict__ eps,   const int* __restrict__ values,
    float* __restrict__ out, int n_out)
{
    const int tid  = threadIdx.x;
    const int lane = tid & 31;
    const int warp = tid >> 5;
    const int cta  = blockIdx.x;

    __shared__ float4 sh4[192];            // one node's cat vector (3 KB)
    __shared__ float s_mu[LATENT], s_lv[LATENT];
    __shared__ float s_hm[HIDDEN];
    __shared__ float s_node[LATENT];
    __shared__ float s_co[HIDDEN];
    __shared__ int   sh_flag, sh_op;

    const unsigned base_z   = g_z;
    const unsigned base_pub = g_pubv;
    grid_sync();                    // single launch-wide rendezvous
    const unsigned epoch = g_gen;   // unique per launch, same for all CTAs

    // ===== ENCODER: node-per-CTA dataflow over levels 7..0 =====
    for (int L = 7; L >= 0; --L) {
        if (cta >= (1 << L)) break;            // done with encoder duties
        const int n  = (1 << L) - 1 + cta;
        const int c1 = 2 * n + 1, c2 = 2 * n + 2;
        const bool leaves = (L == 7);

        if (!leaves) {                         // wait for the two child CTAs
            if (tid == 0)  while (g_nf[c1] != epoch) { }
            if (tid == 32) while (g_nf[c2] != epoch) { }
        }
        __syncthreads();
        __threadfence();                       // acquire child stores

        // gather cat = [emb(values[n]); h(c1); h(c2)] into shared
        if (tid < 192) {
            const float4* src;
            if (tid < 64) {
                src = reinterpret_cast<const float4*>(embed + (size_t)values[n] * HIDDEN) + tid;
            } else if (tid < 128) {
                src = leaves
                    ? reinterpret_cast<const float4*>(embed + (size_t)values[c1] * HIDDEN) + (tid - 64)
                    : reinterpret_cast<const float4*>(g_h + (size_t)c1 * HIDDEN) + (tid - 64);
            } else {
                src = leaves
                    ? reinterpret_cast<const float4*>(embed + (size_t)values[c2] * HIDDEN) + (tid - 128)
                    : reinterpret_cast<const float4*>(g_h + (size_t)c2 * HIDDEN) + (tid - 128);
            }
            sh4[tid] = *src;
        }
        __syncthreads();

        // 768->256 matvec, 4 consecutive rows per warp-iteration (ILP)
        for (int g = warp; g < 64; g += NWARP) {
            const float4* w0 = reinterpret_cast<const float4*>(Wpar + (size_t)(4 * g + 0) * 768);
            const float4* w1 = reinterpret_cast<const float4*>(Wpar + (size_t)(4 * g + 1) * 768);
            const float4* w2 = reinterpret_cast<const float4*>(Wpar + (size_t)(4 * g + 2) * 768);
            const float4* w3 = reinterpret_cast<const float4*>(Wpar + (size_t)(4 * g + 3) * 768);
            float a0 = 0.f, a1 = 0.f, a2 = 0.f, a3 = 0.f;
#pragma unroll
            for (int j = 0; j < 6; ++j) {
                float4 x  = sh4[j * 32 + lane];
                float4 q0 = __ldg(w0 + j * 32 + lane);
                float4 q1 = __ldg(w1 + j * 32 + lane);
                float4 q2 = __ldg(w2 + j * 32 + lane);
                float4 q3 = __ldg(w3 + j * 32 + lane);
                a0 += q0.x * x.x + q0.y * x.y + q0.z * x.z + q0.w * x.w;
                a1 += q1.x * x.x + q1.y * x.y + q1.z * x.z + q1.w * x.w;
                a2 += q2.x * x.x + q2.y * x.y + q2.z * x.z + q2.w * x.w;
                a3 += q3.x * x.x + q3.y * x.y + q3.z * x.z + q3.w * x.w;
            }
#pragma unroll
            for (int o = 16; o; o >>= 1) {     // 4 interleaved reduction chains
                a0 += __shfl_xor_sync(0xffffffffu, a0, o);
                a1 += __shfl_xor_sync(0xffffffffu, a1, o);
                a2 += __shfl_xor_sync(0xffffffffu, a2, o);
                a3 += __shfl_xor_sync(0xffffffffu, a3, o);
            }
            if (lane == 0) {
                float4 bb = *reinterpret_cast<const float4*>(bpar + 4 * g);
                reinterpret_cast<float4*>(g_h + (size_t)n * HIDDEN)[g] =
                    make_float4(a0 + bb.x, a1 + bb.y, a2 + bb.z, a3 + bb.w);
            }
        }
        __threadfence();                       // release h stores
        __syncthreads();
        if (tid == 0 && n != 0) g_nf[n] = epoch;
    }

    if (cta != 0) {
        // ===== ZEROER + CONSUMER =====
        {   // zero this CTA's slice of the poisoned out buffer
            float4 z4 = make_float4(0.f, 0.f, 0.f, 0.f);
            float4* o4 = reinterpret_cast<float4*>(out);
            int n4 = n_out >> 2;
            for (int i = (cta - 1) * NT + tid; i < n4; i += NCONS * NT) o4[i] = z4;
            if (cta == 1) for (int i = (n4 << 2) + tid; i < n_out; i += NT) out[i] = 0.f;
        }
        __threadfence();
        __syncthreads();
        if (tid == 0) {
            atomicAdd((unsigned*)&g_z, 1u);
            while (g_z - base_z < (unsigned)NCONS) { }
        }
        __syncthreads();

        // consume published decoder steps
        for (int s = 0; ; ++s) {
            if (tid == 0) {
                while ((int)(g_pubv - base_pub) <= s) { }
                __threadfence();
                sh_flag = g_dflag[s];
                sh_op   = g_dop[s];
            }
            __syncthreads();
            const int flag = sh_flag;
            if (flag < 0) break;
            const int op = sh_op;

            const float4* cb = reinterpret_cast<const float4*>(g_dco[s]);
            const float4 c0 = __ldcg(cb + lane);
            const float4 c1 = __ldcg(cb + 32 + lane);

            const float* W    = flag ? Wp : Wl;
            const float* bias = flag ? bp : bl;
            float* orow = out + (size_t)op * VOCAB;
            const int gw     = (cta - 1) * NWARP + warp;
            const int stride = NCONS * NWARP * 4;
            for (int r = gw * 4; r < VOCAB; r += stride) {
                float s0 = wdot256c(W + (size_t)(r + 0) * HIDDEN, c0, c1, lane);
                float s1 = wdot256c(W + (size_t)(r + 1) * HIDDEN, c0, c1, lane);
                float s2 = wdot256c(W + (size_t)(r + 2) * HIDDEN, c0, c1, lane);
                float s3 = wdot256c(W + (size_t)(r + 3) * HIDDEN, c0, c1, lane);
                if (lane == 0) {
                    orow[r + 0] = s0 + bias[r + 0];
                    orow[r + 1] = s1 + bias[r + 1];
                    orow[r + 2] = s2 + bias[r + 2];
                    orow[r + 3] = s3 + bias[r + 3];
                }
            }
            __syncthreads();                   // keep sh_flag/sh_op stable
        }
        return;
    }

    // ================= CTA 0: latent + sequential decoder =================
    // mu / logvar from root (g_h[0..255], this CTA's own stores)
    {
        float4 r0 = reinterpret_cast<const float4*>(g_h)[lane];
        float4 r1 = reinterpret_cast<const float4*>(g_h)[32 + lane];
        for (int rr = warp; rr < 2 * LATENT; rr += NWARP) {
            const float* Wr = (rr < LATENT) ? Wmu + (size_t)rr * HIDDEN
                                            : Wlv + (size_t)(rr - LATENT) * HIDDEN;
            float s = wdot256g(Wr, r0, r1, lane);
            if (lane == 0) {
                float v = s + ((rr < LATENT) ? bmu[rr] : blv[rr - LATENT]);
                if (rr < LATENT) s_mu[rr] = v; else s_lv[rr - LATENT] = v;
            }
        }
    }
    // wait for zeroers before writing the mu/logvar tail row
    if (tid == 0) { while (g_z - base_z < (unsigned)NCONS) { } __threadfence(); }
    __syncthreads();
    if (tid < LATENT) {
        float m = s_mu[tid], lv = s_lv[tid];
        out[(size_t)MAXSTEPS * VOCAB + tid]          = m;
        out[(size_t)MAXSTEPS * VOCAB + LATENT + tid] = lv;
        float z = m + eps[tid] * expf(0.5f * lv);
        s_node[tid] = z;
        g_stack[tid] = z;
    }
    __syncthreads();

    // ---- sequential decoder chain; publish each step to the deck ----
    int sp = 1, op = 0, flag;
    {   // phase A for step 0
        float4 zc = reinterpret_cast<const float4*>(s_node)[lane];
        for (int rr = warp; rr < HIDDEN; rr += NWARP) {
            float4 a = __ldg(reinterpret_cast<const float4*>(W1 + (size_t)rr * LATENT) + lane);
            float s = a.x * zc.x + a.y * zc.y + a.z * zc.z + a.w * zc.w;
#pragma unroll
            for (int o = 16; o; o >>= 1) s += __shfl_xor_sync(0xffffffffu, s, o);
            if (lane == 0) { s += b1[rr]; s_hm[rr] = s > 0.f ? s : 0.2f * s; }
        }
        __syncthreads();
        float4 h0 = reinterpret_cast<const float4*>(s_hm)[lane];
        float4 h1 = reinterpret_cast<const float4*>(s_hm)[32 + lane];
        for (int rr = warp; rr < HIDDEN + 1; rr += NWARP) {
            float s = wdot256g(W2 + (size_t)rr * HIDDEN, h0, h1, lane);
            if (lane == 0) {
                s += b2[rr];
                if (rr == 0) sh_flag = (s > 0.f) ? 1 : 0;   // sp-1=0 <= 62 always
                else         s_co[rr - 1] = s;
            }
        }
        __syncthreads();
        flag = sh_flag;
    }

    int it = 0;
    while (true) {
        // publish step `it`
        for (int i = tid; i < HIDDEN; i += NT) g_dco[it][i] = s_co[i];
        if (tid == 0) { g_dflag[it] = flag; g_dop[it] = op; }
        __threadfence();
        __syncthreads();
        if (tid == 0) g_pubv = base_pub + (unsigned)(it + 1);

        // next-state compute (stack + next node)
        int sp_next;
        if (flag) {
            const float4* cb = reinterpret_cast<const float4*>(s_co);
            float4 c0 = cb[lane], c1 = cb[32 + lane];
            for (int j = warp; j < 2 * LATENT; j += NWARP) {
                float s = wdot256c(Wp + (size_t)(VOCAB + j) * HIDDEN, c0, c1, lane);
                if (lane == 0) {
                    float v = s + bp[VOCAB + j];
                    if (j < LATENT) {
                        g_stack[(sp - 1) * LATENT + j] = v;      // ll
                    } else {
                        g_stack[sp * LATENT + (j - LATENT)] = v; // rl
                        s_node[j - LATENT] = v;                  // next node = rl
                    }
                }
            }
            sp_next = sp + 1;
        } else {
            sp_next = sp - 1;
            if (tid < LATENT && sp_next > 0) s_node[tid] = g_stack[(sp_next - 1) * LATENT + tid];
        }
        __syncthreads();

        ++it;
        if (sp_next <= 0 || it >= MAXSTEPS) {   // inactive: publish sentinel
            if (tid == 0) g_dflag[it] = -1;
            __threadfence();
            __syncthreads();
            if (tid == 0) g_pubv = base_pub + (unsigned)(it + 1);
            break;
        }

        // phase A for next step
        {
            float4 zc = reinterpret_cast<const float4*>(s_node)[lane];
            for (int rr = warp; rr < HIDDEN; rr += NWARP) {
                float4 a = __ldg(reinterpret_cast<const float4*>(W1 + (size_t)rr * LATENT) + lane);
                float s = a.x * zc.x + a.y * zc.y + a.z * zc.z + a.w * zc.w;
#pragma unroll
                for (int o = 16; o; o >>= 1) s += __shfl_xor_sync(0xffffffffu, s, o);
                if (lane == 0) { s += b1[rr]; s_hm[rr] = s > 0.f ? s : 0.2f * s; }
            }
            __syncthreads();
            float4 h0 = reinterpret_cast<const float4*>(s_hm)[lane];
            float4 h1 = reinterpret_cast<const float4*>(s_hm)[32 + lane];
            for (int rr = warp; rr < HIDDEN + 1; rr += NWARP) {
                float s = wdot256g(W2 + (size_t)rr * HIDDEN, h0, h1, lane);
                if (lane == 0) {
                    s += b2[rr];
                    if (rr == 0) sh_flag = (s > 0.f && sp_next <= MAXLEN - 1) ? 1 : 0;
                    else         s_co[rr - 1] = s;
                }
            }
            __syncthreads();
            flag = sh_flag;
        }
        op += 1;
        sp = sp_next;
    }
}

extern "C" void kernel_launch(void* const* d_in, const int* in_sizes, int n_in,
                              void* d_out, int out_size) {
    const float* embed = (const float*)d_in[0];
    const float* Wpar  = (const float*)d_in[1];
    const float* bpar  = (const float*)d_in[2];
    const float* Wmu   = (const float*)d_in[3];
    const float* bmu   = (const float*)d_in[4];
    const float* Wlv   = (const float*)d_in[5];
    const float* blv   = (const float*)d_in[6];
    const float* W1    = (const float*)d_in[7];
    const float* b1    = (const float*)d_in[8];
    const float* W2    = (const float*)d_in[9];
    const float* b2    = (const float*)d_in[10];
    const float* Wl    = (const float*)d_in[11];
    const float* bl    = (const float*)d_in[12];
    const float* Wp    = (const float*)d_in[13];
    const float* bp    = (const float*)d_in[14];
    const float* eps   = (const float*)d_in[15];
    const int*   values= (const int*)  d_in[16];
    // d_in[17]=left, d_in[18]=right: fixed complete-tree topology; unused.

    vae_kernel<<<NB, NT>>>(embed, Wpar, bpar, Wmu, bmu, Wlv, blv,
                           W1, b1, W2, b2, Wl, bl, Wp, bp, eps, values,
                           (float*)d_out, out_size);
}

// round 6
// speedup vs baseline: 5.0902x; 1.8192x over previous
#include <cuda_runtime.h>

#define HIDDEN   256
#define LATENT   128
#define VOCAB    32000
#define MAXLEN   64
#define MAXSTEPS 128
#define NB       148
#define NT       256
#define NWARP    (NT/32)
#define NCONS    (NB - 1)          // 147 consumer CTAs
#define NZ       20                // zeroer CTAs: 128..147

// ---------------- device scratch (no allocation allowed) ----------------
__device__ __align__(16) float g_h[255 * HIDDEN];          // internal-node hidden states
__device__ __align__(16) float g_stack[MAXLEN * LATENT];   // decoder stack (CTA 0 only)
__device__ __align__(16) float g_dco[MAXSTEPS + 1][HIDDEN];// published co deck
__device__ int g_dflag[MAXSTEPS + 1];                      // step flag; -1 = sentinel
__device__ int g_dop[MAXSTEPS + 1];                        // step output row
__device__ volatile unsigned g_pf[255 * 8];                // (node,part) done flags, epoch-tagged
// monotonic counters (never reset; survive graph replays)
__device__ volatile unsigned g_z;     // zeroing-done count
__device__ volatile unsigned g_pubv;  // published step count
// entry barrier (sense-reversal; g_gen doubles as the per-launch epoch)
__device__ __align__(128) unsigned g_cnt = 0;
__device__ __align__(128) volatile unsigned g_gen = 0;

__constant__ int c_S[8] = {8, 8, 8, 8, 8, 4, 2, 1};   // CTAs per node, by level

__device__ __forceinline__ void grid_sync() {
    __threadfence();
    __syncthreads();
    if (threadIdx.x == 0) {
        unsigned gen = g_gen;
        if (atomicAdd(&g_cnt, 1u) == NB - 1u) {
            g_cnt = 0;
            __threadfence();
            g_gen = gen + 1u;
        } else {
            while (g_gen == gen) { }
        }
        __threadfence();
    }
    __syncthreads();
}

// warp dot: 256-float row vs lane-resident x, streaming (L2)
__device__ __forceinline__ float wdot256c(const float* __restrict__ row,
                                          float4 c0, float4 c1, int lane) {
    const float4* r4 = reinterpret_cast<const float4*>(row);
    float4 a = __ldcg(r4 + lane);
    float4 b = __ldcg(r4 + 32 + lane);
    float s = a.x * c0.x + a.y * c0.y + a.z * c0.z + a.w * c0.w;
    s      += b.x * c1.x + b.y * c1.y + b.z * c1.z + b.w * c1.w;
#pragma unroll
    for (int o = 16; o; o >>= 1) s += __shfl_xor_sync(0xffffffffu, s, o);
    return s;
}

// 4 interleaved 256-wide dots (rows r0..r0+3 of W, row stride 256), L1-cached
__device__ __forceinline__ float4 wdot256x4(const float* __restrict__ W, int r0,
                                            float4 h0, float4 h1, int lane) {
    const float4* w0 = reinterpret_cast<const float4*>(W + (size_t)(r0 + 0) * HIDDEN);
    const float4* w1 = reinterpret_cast<const float4*>(W + (size_t)(r0 + 1) * HIDDEN);
    const float4* w2 = reinterpret_cast<const float4*>(W + (size_t)(r0 + 2) * HIDDEN);
    const float4* w3 = reinterpret_cast<const float4*>(W + (size_t)(r0 + 3) * HIDDEN);
    float a0, a1, a2, a3;
    {
        float4 q0 = __ldg(w0 + lane), q1 = __ldg(w1 + lane),
               q2 = __ldg(w2 + lane), q3 = __ldg(w3 + lane);
        a0 = q0.x * h0.x + q0.y * h0.y + q0.z * h0.z + q0.w * h0.w;
        a1 = q1.x * h0.x + q1.y * h0.y + q1.z * h0.z + q1.w * h0.w;
        a2 = q2.x * h0.x + q2.y * h0.y + q2.z * h0.z + q2.w * h0.w;
        a3 = q3.x * h0.x + q3.y * h0.y + q3.z * h0.z + q3.w * h0.w;
    }
    {
        float4 q0 = __ldg(w0 + 32 + lane), q1 = __ldg(w1 + 32 + lane),
               q2 = __ldg(w2 + 32 + lane), q3 = __ldg(w3 + 32 + lane);
        a0 += q0.x * h1.x + q0.y * h1.y + q0.z * h1.z + q0.w * h1.w;
        a1 += q1.x * h1.x + q1.y * h1.y + q1.z * h1.z + q1.w * h1.w;
        a2 += q2.x * h1.x + q2.y * h1.y + q2.z * h1.z + q2.w * h1.w;
        a3 += q3.x * h1.x + q3.y * h1.y + q3.z * h1.z + q3.w * h1.w;
    }
#pragma unroll
    for (int o = 16; o; o >>= 1) {
        a0 += __shfl_xor_sync(0xffffffffu, a0, o);
        a1 += __shfl_xor_sync(0xffffffffu, a1, o);
        a2 += __shfl_xor_sync(0xffffffffu, a2, o);
        a3 += __shfl_xor_sync(0xffffffffu, a3, o);
    }
    return make_float4(a0, a1, a2, a3);
}

__global__ void __launch_bounds__(NT, 1) vae_kernel(
    const float* __restrict__ embed, const float* __restrict__ Wpar, const float* __restrict__ bpar,
    const float* __restrict__ Wmu,   const float* __restrict__ bmu,
    const float* __restrict__ Wlv,   const float* __restrict__ blv,
    const float* __restrict__ W1,    const float* __restrict__ b1,
    const float* __restrict__ W2,    const float* __restrict__ b2,
    const float* __restrict__ Wl,    const float* __restrict__ bl,
    const float* __restrict__ Wp,    const float* __restrict__ bp,
    const float* __restrict__ eps,   const int* __restrict__ values,
    float* __restrict__ out, int n_out)
{
    const int tid  = threadIdx.x;
    const int lane = tid & 31;
    const int warp = tid >> 5;
    const int cta  = blockIdx.x;

    __shared__ float4 sh4[192];            // one node's cat vector (3 KB)
    __shared__ float s_mu[LATENT], s_lv[LATENT];
    __shared__ float s_hm[HIDDEN];
    __shared__ float s_node[LATENT];
    __shared__ float s_co[HIDDEN];
    __shared__ int   sh_flag, sh_op;

    const unsigned base_z   = g_z;
    const unsigned base_pub = g_pubv;
    grid_sync();                    // single launch-wide rendezvous
    const unsigned epoch = g_gen;   // unique per launch, same for all CTAs

    if (cta >= 128) {
        // ===== ZEROERS (CTAs 128..147): overlap with encoder =====
        float4 z4 = make_float4(0.f, 0.f, 0.f, 0.f);
        float4* o4 = reinterpret_cast<float4*>(out);
        int n4 = n_out >> 2;
        for (int i = (cta - 128) * NT + tid; i < n4; i += NZ * NT) o4[i] = z4;
        if (cta == 128) for (int i = (n4 << 2) + tid; i < n_out; i += NT) out[i] = 0.f;
        __threadfence();
        __syncthreads();
        if (tid == 0) atomicAdd((unsigned*)&g_z, 1u);
    } else {
        // ===== ENCODER: split-node dataflow, levels 7..0 =====
        for (int L = 7; L >= 0; --L) {
            const int S = c_S[L];
            if (cta >= (1 << L) * S) break;         // done with encoder duty
            const int node = (1 << L) - 1 + cta / S;
            const int part = cta - (cta / S) * S;
            const int c1n = 2 * node + 1, c2n = 2 * node + 2;
            const bool leaves = (L == 7);

            if (!leaves) {                          // wait for all parts of both children
                const int Sc = c_S[L + 1];
                if (tid < Sc)                    while (g_pf[c1n * 8 + tid] != epoch) { }
                if (tid >= 32 && tid < 32 + Sc)  while (g_pf[c2n * 8 + (tid - 32)] != epoch) { }
                __syncthreads();
                __threadfence();                    // acquire child stores
            }

            // gather cat = [emb(values[node]); h(c1); h(c2)] into shared
            if (tid < 192) {
                float4 v;
                if (tid < 64) {
                    v = __ldg(reinterpret_cast<const float4*>(embed + (size_t)values[node] * HIDDEN) + tid);
                } else if (tid < 128) {
                    v = leaves
                      ? __ldg (reinterpret_cast<const float4*>(embed + (size_t)values[c1n] * HIDDEN) + (tid - 64))
                      : __ldcg(reinterpret_cast<const float4*>(g_h + (size_t)c1n * HIDDEN) + (tid - 64));
                } else {
                    v = leaves
                      ? __ldg (reinterpret_cast<const float4*>(embed + (size_t)values[c2n] * HIDDEN) + (tid - 128))
                      : __ldcg(reinterpret_cast<const float4*>(g_h + (size_t)c2n * HIDDEN) + (tid - 128));
                }
                sh4[tid] = v;
            }
            __syncthreads();

            // this part computes row-groups [part*gpp, (part+1)*gpp) of 64
            const int gpp = 64 / S;
            for (int g2 = warp; g2 < gpp; g2 += NWARP) {
                const int grp = part * gpp + g2;
                const float4* w0 = reinterpret_cast<const float4*>(Wpar + (size_t)(4 * grp + 0) * 768);
                const float4* w1 = reinterpret_cast<const float4*>(Wpar + (size_t)(4 * grp + 1) * 768);
                const float4* w2 = reinterpret_cast<const float4*>(Wpar + (size_t)(4 * grp + 2) * 768);
                const float4* w3 = reinterpret_cast<const float4*>(Wpar + (size_t)(4 * grp + 3) * 768);
                float a0 = 0.f, a1 = 0.f, a2 = 0.f, a3 = 0.f;
#pragma unroll
                for (int j = 0; j < 6; ++j) {
                    float4 x  = sh4[j * 32 + lane];
                    float4 q0 = __ldg(w0 + j * 32 + lane);
                    float4 q1 = __ldg(w1 + j * 32 + lane);
                    float4 q2 = __ldg(w2 + j * 32 + lane);
                    float4 q3 = __ldg(w3 + j * 32 + lane);
                    a0 += q0.x * x.x + q0.y * x.y + q0.z * x.z + q0.w * x.w;
                    a1 += q1.x * x.x + q1.y * x.y + q1.z * x.z + q1.w * x.w;
                    a2 += q2.x * x.x + q2.y * x.y + q2.z * x.z + q2.w * x.w;
                    a3 += q3.x * x.x + q3.y * x.y + q3.z * x.z + q3.w * x.w;
                }
#pragma unroll
                for (int o = 16; o; o >>= 1) {
                    a0 += __shfl_xor_sync(0xffffffffu, a0, o);
                    a1 += __shfl_xor_sync(0xffffffffu, a1, o);
                    a2 += __shfl_xor_sync(0xffffffffu, a2, o);
                    a3 += __shfl_xor_sync(0xffffffffu, a3, o);
                }
                if (lane == 0) {
                    float4 bb = __ldg(reinterpret_cast<const float4*>(bpar + 4 * grp));
                    reinterpret_cast<float4*>(g_h + (size_t)node * HIDDEN)[grp] =
                        make_float4(a0 + bb.x, a1 + bb.y, a2 + bb.z, a3 + bb.w);
                }
            }
            __threadfence();                        // release h stores
            __syncthreads();
            if (tid == 0) g_pf[node * 8 + part] = epoch;
        }
    }

    if (cta != 0) {
        // ===== CONSUMERS (CTAs 1..147) =====
        if (tid == 0) while (g_z - base_z < (unsigned)NZ) { }   // out fully zeroed
        __syncthreads();

        for (int s = 0; ; ++s) {
            if (tid == 0) {
                while ((int)(g_pubv - base_pub) <= s) { }
                __threadfence();
                sh_flag = g_dflag[s];
                sh_op   = g_dop[s];
            }
            __syncthreads();
            const int flag = sh_flag;
            if (flag < 0) break;
            const int op = sh_op;

            const float4* cb = reinterpret_cast<const float4*>(g_dco[s]);
            const float4 c0 = __ldcg(cb + lane);
            const float4 c1 = __ldcg(cb + 32 + lane);

            const float* W    = flag ? Wp : Wl;
            const float* bias = flag ? bp : bl;
            float* orow = out + (size_t)op * VOCAB;
            const int gw     = (cta - 1) * NWARP + warp;
            const int stride = NCONS * NWARP * 4;
            for (int r = gw * 4; r < VOCAB; r += stride) {
                float s0 = wdot256c(W + (size_t)(r + 0) * HIDDEN, c0, c1, lane);
                float s1 = wdot256c(W + (size_t)(r + 1) * HIDDEN, c0, c1, lane);
                float s2 = wdot256c(W + (size_t)(r + 2) * HIDDEN, c0, c1, lane);
                float s3 = wdot256c(W + (size_t)(r + 3) * HIDDEN, c0, c1, lane);
                if (lane == 0) {
                    orow[r + 0] = s0 + bias[r + 0];
                    orow[r + 1] = s1 + bias[r + 1];
                    orow[r + 2] = s2 + bias[r + 2];
                    orow[r + 3] = s3 + bias[r + 3];
                }
            }
            __syncthreads();                   // keep sh_flag/sh_op stable
        }
        return;
    }

    // ================= CTA 0: latent + sequential decoder =================
    // wait for all 8 root parts
    if (tid < 8) while (g_pf[0 * 8 + tid] != epoch) { }
    __syncthreads();
    __threadfence();

    {   // mu / logvar from root, 4-row ILP
        const float4* rb = reinterpret_cast<const float4*>(g_h);
        float4 r0c = __ldcg(rb + lane);
        float4 r1c = __ldcg(rb + 32 + lane);
        for (int g = warp; g < 64; g += NWARP) {
            int r0 = 4 * g;
            const float* W    = (r0 < LATENT) ? Wmu : Wlv;
            const float* bb   = (r0 < LATENT) ? bmu : blv;
            int rr = (r0 < LATENT) ? r0 : r0 - LATENT;
            float4 a = wdot256x4(W, rr, r0c, r1c, lane);
            if (lane == 0) {
                float4 b4 = __ldg(reinterpret_cast<const float4*>(bb + rr));
                float* dst = (r0 < LATENT) ? (s_mu + rr) : (s_lv + rr);
                dst[0] = a.x + b4.x; dst[1] = a.y + b4.y;
                dst[2] = a.z + b4.z; dst[3] = a.w + b4.w;
            }
        }
    }
    if (tid == 0) { while (g_z - base_z < (unsigned)NZ) { } __threadfence(); }
    __syncthreads();
    if (tid < LATENT) {
        float m = s_mu[tid], lv = s_lv[tid];
        out[(size_t)MAXSTEPS * VOCAB + tid]          = m;
        out[(size_t)MAXSTEPS * VOCAB + LATENT + tid] = lv;
        float z = m + eps[tid] * expf(0.5f * lv);
        s_node[tid] = z;
        g_stack[tid] = z;
    }
    __syncthreads();

    int sp = 1, op = 0, flag, it = 0;
    while (true) {
        // ---- phase A: hmid = leaky(W1@node + b1); co/flag = W2@hmid + b2 ----
        {
            float4 zc = reinterpret_cast<const float4*>(s_node)[lane];
            for (int g = warp; g < 32; g += NWARP) {       // 128.. wait: 256 rows/4 = 64 groups
            }
            for (int g = warp; g < 64; g += NWARP) {
                int r0 = 4 * g;
                const float4* w0 = reinterpret_cast<const float4*>(W1 + (size_t)(r0 + 0) * LATENT);
                const float4* w1 = reinterpret_cast<const float4*>(W1 + (size_t)(r0 + 1) * LATENT);
                const float4* w2 = reinterpret_cast<const float4*>(W1 + (size_t)(r0 + 2) * LATENT);
                const float4* w3 = reinterpret_cast<const float4*>(W1 + (size_t)(r0 + 3) * LATENT);
                float4 q0 = __ldg(w0 + lane), q1 = __ldg(w1 + lane),
                       q2 = __ldg(w2 + lane), q3 = __ldg(w3 + lane);
                float a0 = q0.x * zc.x + q0.y * zc.y + q0.z * zc.z + q0.w * zc.w;
                float a1 = q1.x * zc.x + q1.y * zc.y + q1.z * zc.z + q1.w * zc.w;
                float a2 = q2.x * zc.x + q2.y * zc.y + q2.z * zc.z + q2.w * zc.w;
                float a3 = q3.x * zc.x + q3.y * zc.y + q3.z * zc.z + q3.w * zc.w;
#pragma unroll
                for (int o = 16; o; o >>= 1) {
                    a0 += __shfl_xor_sync(0xffffffffu, a0, o);
                    a1 += __shfl_xor_sync(0xffffffffu, a1, o);
                    a2 += __shfl_xor_sync(0xffffffffu, a2, o);
                    a3 += __shfl_xor_sync(0xffffffffu, a3, o);
                }
                if (lane == 0) {
                    float4 b4 = __ldg(reinterpret_cast<const float4*>(b1 + r0));
                    float v0 = a0 + b4.x, v1 = a1 + b4.y, v2 = a2 + b4.z, v3 = a3 + b4.w;
                    s_hm[r0 + 0] = v0 > 0.f ? v0 : 0.2f * v0;
                    s_hm[r0 + 1] = v1 > 0.f ? v1 : 0.2f * v1;
                    s_hm[r0 + 2] = v2 > 0.f ? v2 : 0.2f * v2;
                    s_hm[r0 + 3] = v3 > 0.f ? v3 : 0.2f * v3;
                }
            }
            __syncthreads();
            float4 h0 = reinterpret_cast<const float4*>(s_hm)[lane];
            float4 h1 = reinterpret_cast<const float4*>(s_hm)[32 + lane];
            for (int g = warp; g < 64; g += NWARP) {
                int r0 = 4 * g;
                float4 a = wdot256x4(W2, r0, h0, h1, lane);
                if (lane == 0) {
                    float4 b4 = __ldg(reinterpret_cast<const float4*>(b2 + r0));
                    float v0 = a.x + b4.x;
                    if (r0 == 0) sh_flag = (v0 > 0.f && sp <= MAXLEN - 1) ? 1 : 0;
                    else         s_co[r0 - 1] = v0;
                    s_co[r0 + 0] = a.y + b4.y;
                    s_co[r0 + 1] = a.z + b4.z;
                    s_co[r0 + 2] = a.w + b4.w;
                }
            }
            if (warp == 7) {   // row 256
                float4 h0b = reinterpret_cast<const float4*>(s_hm)[lane];
                float4 h1b = reinterpret_cast<const float4*>(s_hm)[32 + lane];
                const float4* wr = reinterpret_cast<const float4*>(W2 + (size_t)256 * HIDDEN);
                float4 qa = __ldg(wr + lane), qb = __ldg(wr + 32 + lane);
                float s = qa.x * h0b.x + qa.y * h0b.y + qa.z * h0b.z + qa.w * h0b.w
                        + qb.x * h1b.x + qb.y * h1b.y + qb.z * h1b.z + qb.w * h1b.w;
#pragma unroll
                for (int o = 16; o; o >>= 1) s += __shfl_xor_sync(0xffffffffu, s, o);
                if (lane == 0) s_co[255] = s + __ldg(b2 + 256);
            }
            __syncthreads();
            flag = sh_flag;
        }

        // ---- publish step `it` ----
        if (tid < 64) reinterpret_cast<float4*>(g_dco[it])[tid] =
                          reinterpret_cast<const float4*>(s_co)[tid];
        if (tid == 0) { g_dflag[it] = flag; g_dop[it] = op; }
        __threadfence();
        __syncthreads();
        if (tid == 0) g_pubv = base_pub + (unsigned)(it + 1);

        // ---- next-state compute ----
        int sp_next;
        if (flag) {
            float4 c0 = reinterpret_cast<const float4*>(s_co)[lane];
            float4 c1 = reinterpret_cast<const float4*>(s_co)[32 + lane];
            for (int g = warp; g < 64; g += NWARP) {
                int j0 = 4 * g;
                float4 a = wdot256x4(Wp + (size_t)VOCAB * HIDDEN, j0, c0, c1, lane);
                if (lane == 0) {
                    float4 b4 = __ldg(reinterpret_cast<const float4*>(bp + VOCAB + j0));
                    float v[4] = {a.x + b4.x, a.y + b4.y, a.z + b4.z, a.w + b4.w};
#pragma unroll
                    for (int i = 0; i < 4; ++i) {
                        int j = j0 + i;
                        if (j < LATENT) {
                            g_stack[(sp - 1) * LATENT + j] = v[i];      // ll
                        } else {
                            g_stack[sp * LATENT + (j - LATENT)] = v[i]; // rl
                            s_node[j - LATENT] = v[i];                  // next node = rl
                        }
                    }
                }
            }
            sp_next = sp + 1;
        } else {
            sp_next = sp - 1;
            if (tid < LATENT && sp_next > 0) s_node[tid] = g_stack[(sp_next - 1) * LATENT + tid];
        }
        __syncthreads();

        ++it;
        if (sp_next <= 0 || it >= MAXSTEPS) {   // inactive: publish sentinel
            if (tid == 0) g_dflag[it] = -1;
            __threadfence();
            __syncthreads();
            if (tid == 0) g_pubv = base_pub + (unsigned)(it + 1);
            break;
        }
        op += 1;
        sp = sp_next;
    }
}

extern "C" void kernel_launch(void* const* d_in, const int* in_sizes, int n_in,
                              void* d_out, int out_size) {
    const float* embed = (const float*)d_in[0];
    const float* Wpar  = (const float*)d_in[1];
    const float* bpar  = (const float*)d_in[2];
    const float* Wmu   = (const float*)d_in[3];
    const float* bmu   = (const float*)d_in[4];
    const float* Wlv   = (const float*)d_in[5];
    const float* blv   = (const float*)d_in[6];
    const float* W1    = (const float*)d_in[7];
    const float* b1    = (const float*)d_in[8];
    const float* W2    = (const float*)d_in[9];
    const float* b2    = (const float*)d_in[10];
    const float* Wl    = (const float*)d_in[11];
    const float* bl    = (const float*)d_in[12];
    const float* Wp    = (const float*)d_in[13];
    const float* bp    = (const float*)d_in[14];
    const float* eps   = (const float*)d_in[15];
    const int*   values= (const int*)  d_in[16];
    // d_in[17]=left, d_in[18]=right: fixed complete-tree topology; unused.

    vae_kernel<<<NB, NT>>>(embed, Wpar, bpar, Wmu, bmu, Wlv, blv,
                           W1, b1, W2, b2, Wl, bl, Wp, bp, eps, values,
                           (float*)d_out, out_size);
}

// round 7
// speedup vs baseline: 5.9584x; 1.1706x over previous
#include <cuda_runtime.h>

#define HIDDEN   256
#define LATENT   128
#define VOCAB    32000
#define MAXLEN   64
#define MAXSTEPS 128
#define NB       148
#define NT       256
#define NWARP    (NT/32)
#define NCONS    (NB - 1)          // 147 consumer CTAs

// ---------------- device scratch (no allocation allowed) ----------------
__device__ __align__(16) float g_h[255 * HIDDEN];           // encoder hidden states
__device__ __align__(16) float g_dco[MAXSTEPS + 1][HIDDEN]; // published co deck
__device__ int g_dflag[MAXSTEPS + 1];                       // step flag; -1 = sentinel
__device__ int g_dop[MAXSTEPS + 1];                         // step output row / final count
__device__ unsigned g_pf[255 * 8];                          // (node,part) flags, epoch-tagged
__device__ unsigned g_dtag[MAXSTEPS + 1];                   // deck slot tags, epoch-tagged
__device__ unsigned g_ticket = 0;                           // monotonic launch ticket

__constant__ int c_S[8] = {8, 8, 8, 8, 8, 4, 2, 1};   // CTAs per node, by level

// ---- scoped acquire/release (no full MEMBAR on the critical path) ----
__device__ __forceinline__ void st_rel(unsigned* p, unsigned v) {
    asm volatile("st.release.gpu.u32 [%0], %1;" :: "l"(p), "r"(v) : "memory");
}
__device__ __forceinline__ unsigned ld_acq(const unsigned* p) {
    unsigned v;
    asm volatile("ld.acquire.gpu.u32 %0, [%1];" : "=r"(v) : "l"(p) : "memory");
    return v;
}

// warp dot: 256-float row vs lane-resident x, streaming (L2)
__device__ __forceinline__ float wdot256c(const float* __restrict__ row,
                                          float4 c0, float4 c1, int lane) {
    const float4* r4 = reinterpret_cast<const float4*>(row);
    float4 a = __ldcg(r4 + lane);
    float4 b = __ldcg(r4 + 32 + lane);
    float s = a.x * c0.x + a.y * c0.y + a.z * c0.z + a.w * c0.w;
    s      += b.x * c1.x + b.y * c1.y + b.z * c1.z + b.w * c1.w;
#pragma unroll
    for (int o = 16; o; o >>= 1) s += __shfl_xor_sync(0xffffffffu, s, o);
    return s;
}

// 4 interleaved 256-wide dots (rows r0..r0+3 of W), L1-cached
__device__ __forceinline__ float4 wdot256x4(const float* __restrict__ W, int r0,
                                            float4 h0, float4 h1, int lane) {
    const float4* w0 = reinterpret_cast<const float4*>(W + (size_t)(r0 + 0) * HIDDEN);
    const float4* w1 = reinterpret_cast<const float4*>(W + (size_t)(r0 + 1) * HIDDEN);
    const float4* w2 = reinterpret_cast<const float4*>(W + (size_t)(r0 + 2) * HIDDEN);
    const float4* w3 = reinterpret_cast<const float4*>(W + (size_t)(r0 + 3) * HIDDEN);
    float a0, a1, a2, a3;
    {
        float4 q0 = __ldg(w0 + lane), q1 = __ldg(w1 + lane),
               q2 = __ldg(w2 + lane), q3 = __ldg(w3 + lane);
        a0 = q0.x * h0.x + q0.y * h0.y + q0.z * h0.z + q0.w * h0.w;
        a1 = q1.x * h0.x + q1.y * h0.y + q1.z * h0.z + q1.w * h0.w;
        a2 = q2.x * h0.x + q2.y * h0.y + q2.z * h0.z + q2.w * h0.w;
        a3 = q3.x * h0.x + q3.y * h0.y + q3.z * h0.z + q3.w * h0.w;
    }
    {
        float4 q0 = __ldg(w0 + 32 + lane), q1 = __ldg(w1 + 32 + lane),
               q2 = __ldg(w2 + 32 + lane), q3 = __ldg(w3 + 32 + lane);
        a0 += q0.x * h1.x + q0.y * h1.y + q0.z * h1.z + q0.w * h1.w;
        a1 += q1.x * h1.x + q1.y * h1.y + q1.z * h1.z + q1.w * h1.w;
        a2 += q2.x * h1.x + q2.y * h1.y + q2.z * h1.z + q2.w * h1.w;
        a3 += q3.x * h1.x + q3.y * h1.y + q3.z * h1.z + q3.w * h1.w;
    }
#pragma unroll
    for (int o = 16; o; o >>= 1) {
        a0 += __shfl_xor_sync(0xffffffffu, a0, o);
        a1 += __shfl_xor_sync(0xffffffffu, a1, o);
        a2 += __shfl_xor_sync(0xffffffffu, a2, o);
        a3 += __shfl_xor_sync(0xffffffffu, a3, o);
    }
    return make_float4(a0, a1, a2, a3);
}

__global__ void __launch_bounds__(NT, 1) vae_kernel(
    const float* __restrict__ embed, const float* __restrict__ Wpar, const float* __restrict__ bpar,
    const float* __restrict__ Wmu,   const float* __restrict__ bmu,
    const float* __restrict__ Wlv,   const float* __restrict__ blv,
    const float* __restrict__ W1,    const float* __restrict__ b1,
    const float* __restrict__ W2,    const float* __restrict__ b2,
    const float* __restrict__ Wl,    const float* __restrict__ bl,
    const float* __restrict__ Wp,    const float* __restrict__ bp,
    const float* __restrict__ eps,   const int* __restrict__ values,
    float* __restrict__ out)
{
    const int tid  = threadIdx.x;
    const int lane = tid & 31;
    const int warp = tid >> 5;
    const int cta  = blockIdx.x;

    __shared__ float4 sh4[192];            // one node's cat vector (3 KB)
    __shared__ float s_stack[MAXLEN * LATENT];  // decoder stack in SMEM (32 KB)
    __shared__ float s_mu[LATENT], s_lv[LATENT];
    __shared__ float s_hm[HIDDEN];
    __shared__ float s_node[LATENT];
    __shared__ float s_co[HIDDEN];
    __shared__ int   sh_flag;
    __shared__ unsigned s_epoch;

    // per-launch epoch without any grid barrier: launches are stream-serialized,
    // so the 148 tickets of one launch share the same quotient.
    if (tid == 0) s_epoch = (atomicAdd(&g_ticket, 1u) / NB) + 1u;
    __syncthreads();
    const unsigned epoch = s_epoch;

    // ===== ENCODER: split-node dataflow, levels 7..0 (CTAs 0..127) =====
    for (int L = 7; L >= 0; --L) {
        const int S = c_S[L];
        if (cta >= (1 << L) * S) break;         // done with encoder duty
        const int node = (1 << L) - 1 + cta / S;
        const int part = cta - (cta / S) * S;
        const int c1n = 2 * node + 1, c2n = 2 * node + 2;
        const bool leaves = (L == 7);

        if (!leaves) {                          // wait for all parts of both children
            const int Sc = c_S[L + 1];
            if (tid < Sc)                    while (ld_acq(&g_pf[c1n * 8 + tid]) != epoch) { }
            if (tid >= 32 && tid < 32 + Sc)  while (ld_acq(&g_pf[c2n * 8 + (tid - 32)]) != epoch) { }
            __syncthreads();
        }

        // gather cat = [emb(values[node]); h(c1); h(c2)] into shared
        if (tid < 192) {
            float4 v;
            if (tid < 64) {
                v = __ldg(reinterpret_cast<const float4*>(embed + (size_t)values[node] * HIDDEN) + tid);
            } else if (tid < 128) {
                v = leaves
                  ? __ldg (reinterpret_cast<const float4*>(embed + (size_t)values[c1n] * HIDDEN) + (tid - 64))
                  : __ldcg(reinterpret_cast<const float4*>(g_h + (size_t)c1n * HIDDEN) + (tid - 64));
            } else {
                v = leaves
                  ? __ldg (reinterpret_cast<const float4*>(embed + (size_t)values[c2n] * HIDDEN) + (tid - 128))
                  : __ldcg(reinterpret_cast<const float4*>(g_h + (size_t)c2n * HIDDEN) + (tid - 128));
            }
            sh4[tid] = v;
        }
        __syncthreads();

        // this part computes row-groups [part*gpp, (part+1)*gpp) of 64
        const int gpp = 64 / S;
        for (int g2 = warp; g2 < gpp; g2 += NWARP) {
            const int grp = part * gpp + g2;
            const float4* w0 = reinterpret_cast<const float4*>(Wpar + (size_t)(4 * grp + 0) * 768);
            const float4* w1 = reinterpret_cast<const float4*>(Wpar + (size_t)(4 * grp + 1) * 768);
            const float4* w2 = reinterpret_cast<const float4*>(Wpar + (size_t)(4 * grp + 2) * 768);
            const float4* w3 = reinterpret_cast<const float4*>(Wpar + (size_t)(4 * grp + 3) * 768);
            float a0 = 0.f, a1 = 0.f, a2 = 0.f, a3 = 0.f;
#pragma unroll
            for (int j = 0; j < 6; ++j) {
                float4 x  = sh4[j * 32 + lane];
                float4 q0 = __ldg(w0 + j * 32 + lane);
                float4 q1 = __ldg(w1 + j * 32 + lane);
                float4 q2 = __ldg(w2 + j * 32 + lane);
                float4 q3 = __ldg(w3 + j * 32 + lane);
                a0 += q0.x * x.x + q0.y * x.y + q0.z * x.z + q0.w * x.w;
                a1 += q1.x * x.x + q1.y * x.y + q1.z * x.z + q1.w * x.w;
                a2 += q2.x * x.x + q2.y * x.y + q2.z * x.z + q2.w * x.w;
                a3 += q3.x * x.x + q3.y * x.y + q3.z * x.z + q3.w * x.w;
            }
#pragma unroll
            for (int o = 16; o; o >>= 1) {
                a0 += __shfl_xor_sync(0xffffffffu, a0, o);
                a1 += __shfl_xor_sync(0xffffffffu, a1, o);
                a2 += __shfl_xor_sync(0xffffffffu, a2, o);
                a3 += __shfl_xor_sync(0xffffffffu, a3, o);
            }
            if (lane == 0) {
                float4 bb = __ldg(reinterpret_cast<const float4*>(bpar + 4 * grp));
                reinterpret_cast<float4*>(g_h + (size_t)node * HIDDEN)[grp] =
                    make_float4(a0 + bb.x, a1 + bb.y, a2 + bb.z, a3 + bb.w);
            }
        }
        __syncthreads();                        // all parts' stores issued
        if (tid == 0) st_rel(&g_pf[node * 8 + part], epoch);
    }

    if (cta != 0) {
        // ===== CONSUMERS (CTAs 1..147), warp-autonomous =====
        int opf = MAXSTEPS;
        for (int s = 0; ; ++s) {
            while (ld_acq(&g_dtag[s]) != epoch) { }
            const int flag = g_dflag[s];
            if (flag < 0) { opf = g_dop[s]; break; }
            const int op = g_dop[s];

            const float4* cb = reinterpret_cast<const float4*>(g_dco[s]);
            const float4 c0 = __ldcg(cb + lane);
            const float4 c1 = __ldcg(cb + 32 + lane);

            const float* W    = flag ? Wp : Wl;
            const float* bias = flag ? bp : bl;
            float* orow = out + (size_t)op * VOCAB;
            const int gw     = (cta - 1) * NWARP + warp;
            const int stride = NCONS * NWARP * 4;
            for (int r = gw * 4; r < VOCAB; r += stride) {
                float s0 = wdot256c(W + (size_t)(r + 0) * HIDDEN, c0, c1, lane);
                float s1 = wdot256c(W + (size_t)(r + 1) * HIDDEN, c0, c1, lane);
                float s2 = wdot256c(W + (size_t)(r + 2) * HIDDEN, c0, c1, lane);
                float s3 = wdot256c(W + (size_t)(r + 3) * HIDDEN, c0, c1, lane);
                if (lane == 0) {
                    orow[r + 0] = s0 + bias[r + 0];
                    orow[r + 1] = s1 + bias[r + 1];
                    orow[r + 2] = s2 + bias[r + 2];
                    orow[r + 3] = s3 + bias[r + 3];
                }
            }
        }
        // zero only the never-written rows [opf .. MAXSTEPS) (out is poisoned)
        {
            float4 z4 = make_float4(0.f, 0.f, 0.f, 0.f);
            float4* o4 = reinterpret_cast<float4*>(out);
            const int i0 = opf * (VOCAB / 4);
            const int i1 = MAXSTEPS * (VOCAB / 4);
            for (int i = i0 + cta * NT + tid; i < i1; i += NB * NT) o4[i] = z4;
        }
        return;
    }

    // ================= CTA 0: latent + sequential decoder =================
    if (tid < 8) while (ld_acq(&g_pf[tid]) != epoch) { }   // all 8 root parts
    __syncthreads();

    {   // mu / logvar from root, 4-row ILP
        const float4* rb = reinterpret_cast<const float4*>(g_h);
        float4 r0c = __ldcg(rb + lane);
        float4 r1c = __ldcg(rb + 32 + lane);
        for (int g = warp; g < 64; g += NWARP) {
            int r0 = 4 * g;
            const float* W    = (r0 < LATENT) ? Wmu : Wlv;
            const float* bb   = (r0 < LATENT) ? bmu : blv;
            int rr = (r0 < LATENT) ? r0 : r0 - LATENT;
            float4 a = wdot256x4(W, rr, r0c, r1c, lane);
            if (lane == 0) {
                float4 b4 = __ldg(reinterpret_cast<const float4*>(bb + rr));
                float* dst = (r0 < LATENT) ? (s_mu + rr) : (s_lv + rr);
                dst[0] = a.x + b4.x; dst[1] = a.y + b4.y;
                dst[2] = a.z + b4.z; dst[3] = a.w + b4.w;
            }
        }
    }
    __syncthreads();
    if (tid < LATENT) {
        float m = s_mu[tid], lv = s_lv[tid];
        out[(size_t)MAXSTEPS * VOCAB + tid]          = m;
        out[(size_t)MAXSTEPS * VOCAB + LATENT + tid] = lv;
        float z = m + eps[tid] * __expf(0.5f * lv);
        s_node[tid] = z;
        s_stack[tid] = z;
    }
    __syncthreads();

    int sp = 1, op = 0, it = 0;
    while (true) {
        // ---- phase A: hmid = leaky(W1@node + b1); co/flag = W2@hmid + b2 ----
        {
            float4 zc = reinterpret_cast<const float4*>(s_node)[lane];
            for (int g = warp; g < 64; g += NWARP) {
                int r0 = 4 * g;
                const float4* w0 = reinterpret_cast<const float4*>(W1 + (size_t)(r0 + 0) * LATENT);
                const float4* w1 = reinterpret_cast<const float4*>(W1 + (size_t)(r0 + 1) * LATENT);
                const float4* w2 = reinterpret_cast<const float4*>(W1 + (size_t)(r0 + 2) * LATENT);
                const float4* w3 = reinterpret_cast<const float4*>(W1 + (size_t)(r0 + 3) * LATENT);
                float4 q0 = __ldg(w0 + lane), q1 = __ldg(w1 + lane),
                       q2 = __ldg(w2 + lane), q3 = __ldg(w3 + lane);
                float a0 = q0.x * zc.x + q0.y * zc.y + q0.z * zc.z + q0.w * zc.w;
                float a1 = q1.x * zc.x + q1.y * zc.y + q1.z * zc.z + q1.w * zc.w;
                float a2 = q2.x * zc.x + q2.y * zc.y + q2.z * zc.z + q2.w * zc.w;
                float a3 = q3.x * zc.x + q3.y * zc.y + q3.z * zc.z + q3.w * zc.w;
#pragma unroll
                for (int o = 16; o; o >>= 1) {
                    a0 += __shfl_xor_sync(0xffffffffu, a0, o);
                    a1 += __shfl_xor_sync(0xffffffffu, a1, o);
                    a2 += __shfl_xor_sync(0xffffffffu, a2, o);
                    a3 += __shfl_xor_sync(0xffffffffu, a3, o);
                }
                if (lane == 0) {
                    float4 b4 = __ldg(reinterpret_cast<const float4*>(b1 + r0));
                    float v0 = a0 + b4.x, v1 = a1 + b4.y, v2 = a2 + b4.z, v3 = a3 + b4.w;
                    s_hm[r0 + 0] = v0 > 0.f ? v0 : 0.2f * v0;
                    s_hm[r0 + 1] = v1 > 0.f ? v1 : 0.2f * v1;
                    s_hm[r0 + 2] = v2 > 0.f ? v2 : 0.2f * v2;
                    s_hm[r0 + 3] = v3 > 0.f ? v3 : 0.2f * v3;
                }
            }
            __syncthreads();
            float4 h0 = reinterpret_cast<const float4*>(s_hm)[lane];
            float4 h1 = reinterpret_cast<const float4*>(s_hm)[32 + lane];
            for (int g = warp; g < 64; g += NWARP) {
                int r0 = 4 * g;
                float4 a = wdot256x4(W2, r0, h0, h1, lane);
                if (lane == 0) {
                    float4 b4 = __ldg(reinterpret_cast<const float4*>(b2 + r0));
                    float v0 = a.x + b4.x;
                    if (r0 == 0) sh_flag = (v0 > 0.f && sp <= MAXLEN - 1) ? 1 : 0;
                    else         s_co[r0 - 1] = v0;
                    s_co[r0 + 0] = a.y + b4.y;
                    s_co[r0 + 1] = a.z + b4.z;
                    s_co[r0 + 2] = a.w + b4.w;
                }
            }
            if (warp == 7) {   // row 256
                const float4* wr = reinterpret_cast<const float4*>(W2 + (size_t)256 * HIDDEN);
                float4 qa = __ldg(wr + lane), qb = __ldg(wr + 32 + lane);
                float s = qa.x * h0.x + qa.y * h0.y + qa.z * h0.z + qa.w * h0.w
                        + qb.x * h1.x + qb.y * h1.y + qb.z * h1.z + qb.w * h1.w;
#pragma unroll
                for (int o = 16; o; o >>= 1) s += __shfl_xor_sync(0xffffffffu, s, o);
                if (lane == 0) s_co[255] = s + __ldg(b2 + 256);
            }
            __syncthreads();
        }
        const int flag = sh_flag;

        // ---- publish step `it` (consumers start logits immediately) ----
        if (tid < 64) reinterpret_cast<float4*>(g_dco[it])[tid] =
                          reinterpret_cast<const float4*>(s_co)[tid];
        if (tid == 0) { g_dflag[it] = flag; g_dop[it] = op; }
        __syncthreads();
        if (tid == 0) st_rel(&g_dtag[it], epoch);

        // ---- next-state compute ----
        int sp_next;
        if (flag) {
            float4 c0 = reinterpret_cast<const float4*>(s_co)[lane];
            float4 c1 = reinterpret_cast<const float4*>(s_co)[32 + lane];
            for (int g = warp; g < 64; g += NWARP) {
                int j0 = 4 * g;
                float4 a = wdot256x4(Wp + (size_t)VOCAB * HIDDEN, j0, c0, c1, lane);
                if (lane == 0) {
                    float4 b4 = __ldg(reinterpret_cast<const float4*>(bp + VOCAB + j0));
                    float v[4] = {a.x + b4.x, a.y + b4.y, a.z + b4.z, a.w + b4.w};
#pragma unroll
                    for (int i = 0; i < 4; ++i) {
                        int j = j0 + i;
                        if (j < LATENT) {
                            s_stack[(sp - 1) * LATENT + j] = v[i];      // ll
                        } else {
                            s_stack[sp * LATENT + (j - LATENT)] = v[i]; // rl
                            s_node[j - LATENT] = v[i];                  // next node = rl
                        }
                    }
                }
            }
            sp_next = sp + 1;
        } else {
            sp_next = sp - 1;
            if (tid < LATENT && sp_next > 0) s_node[tid] = s_stack[(sp_next - 1) * LATENT + tid];
        }
        __syncthreads();

        ++op; ++it;
        if (sp_next <= 0 || it >= MAXSTEPS) {   // publish sentinel with final row count
            if (tid == 0) {
                g_dflag[it] = -1;
                g_dop[it]   = op;
                st_rel(&g_dtag[it], epoch);
            }
            break;
        }
        sp = sp_next;
    }

    // CTA 0 helps zero the never-written rows
    {
        __syncthreads();
        float4 z4 = make_float4(0.f, 0.f, 0.f, 0.f);
        float4* o4 = reinterpret_cast<float4*>(out);
        const int i0 = op * (VOCAB / 4);
        const int i1 = MAXSTEPS * (VOCAB / 4);
        for (int i = i0 + cta * NT + tid; i < i1; i += NB * NT) o4[i] = z4;
    }
}

extern "C" void kernel_launch(void* const* d_in, const int* in_sizes, int n_in,
                              void* d_out, int out_size) {
    const float* embed = (const float*)d_in[0];
    const float* Wpar  = (const float*)d_in[1];
    const float* bpar  = (const float*)d_in[2];
    const float* Wmu   = (const float*)d_in[3];
    const float* bmu   = (const float*)d_in[4];
    const float* Wlv   = (const float*)d_in[5];
    const float* blv   = (const float*)d_in[6];
    const float* W1    = (const float*)d_in[7];
    const float* b1    = (const float*)d_in[8];
    const float* W2    = (const float*)d_in[9];
    const float* b2    = (const float*)d_in[10];
    const float* Wl    = (const float*)d_in[11];
    const float* bl    = (const float*)d_in[12];
    const float* Wp    = (const float*)d_in[13];
    const float* bp    = (const float*)d_in[14];
    const float* eps   = (const float*)d_in[15];
    const int*   values= (const int*)  d_in[16];
    // d_in[17]=left, d_in[18]=right: fixed complete-tree topology; unused.

    vae_kernel<<<NB, NT>>>(embed, Wpar, bpar, Wmu, bmu, Wlv, blv,
                           W1, b1, W2, b2, Wl, bl, Wp, bp, eps, values,
                           (float*)d_out);
}

// round 8
// speedup vs baseline: 6.3129x; 1.0595x over previous
#include <cuda_runtime.h>

#define HIDDEN   256
#define LATENT   128
#define VOCAB    32000
#define MAXLEN   64
#define MAXSTEPS 128
#define NB       148
#define NT       256
#define NWARP    (NT/32)
#define NCONS    (NB - 1)          // 147 consumer CTAs
#define NZ       20                // zeroer CTAs: 128..147

// ---------------- device scratch (no allocation allowed) ----------------
__device__ __align__(16) float g_h[255 * HIDDEN];           // encoder hidden states
__device__ __align__(16) float g_dco[MAXSTEPS + 1][HIDDEN]; // published co deck
__device__ int g_dflag[MAXSTEPS + 1];                       // step flag; -1 = sentinel
__device__ int g_dop[MAXSTEPS + 1];                         // step output row
__device__ unsigned g_pf[255 * 8];                          // (node,part) flags, epoch-tagged
__device__ unsigned g_dtag[MAXSTEPS + 1];                   // deck slot tags, epoch-tagged
__device__ unsigned g_zf[NZ];                               // zeroer flags, epoch-tagged
__device__ unsigned g_ticket = 0;                           // monotonic launch ticket

__constant__ int c_S[8] = {8, 8, 8, 8, 8, 4, 2, 1};   // CTAs per node, by level

// ---- scoped acquire/release ----
__device__ __forceinline__ void st_rel(unsigned* p, unsigned v) {
    asm volatile("st.release.gpu.u32 [%0], %1;" :: "l"(p), "r"(v) : "memory");
}
__device__ __forceinline__ unsigned ld_acq(const unsigned* p) {
    unsigned v;
    asm volatile("ld.acquire.gpu.u32 %0, [%1];" : "=r"(v) : "l"(p) : "memory");
    return v;
}

// warp dot: 256-float row vs lane-resident x, streaming (L2)
__device__ __forceinline__ float wdot256c(const float* __restrict__ row,
                                          float4 c0, float4 c1, int lane) {
    const float4* r4 = reinterpret_cast<const float4*>(row);
    float4 a = __ldcg(r4 + lane);
    float4 b = __ldcg(r4 + 32 + lane);
    float s = a.x * c0.x + a.y * c0.y + a.z * c0.z + a.w * c0.w;
    s      += b.x * c1.x + b.y * c1.y + b.z * c1.z + b.w * c1.w;
#pragma unroll
    for (int o = 16; o; o >>= 1) s += __shfl_xor_sync(0xffffffffu, s, o);
    return s;
}

// 4 interleaved 256-wide dots (rows r0..r0+3 of W), L1-cached
__device__ __forceinline__ float4 wdot256x4(const float* __restrict__ W, int r0,
                                            float4 h0, float4 h1, int lane) {
    const float4* w0 = reinterpret_cast<const float4*>(W + (size_t)(r0 + 0) * HIDDEN);
    const float4* w1 = reinterpret_cast<const float4*>(W + (size_t)(r0 + 1) * HIDDEN);
    const float4* w2 = reinterpret_cast<const float4*>(W + (size_t)(r0 + 2) * HIDDEN);
    const float4* w3 = reinterpret_cast<const float4*>(W + (size_t)(r0 + 3) * HIDDEN);
    float a0, a1, a2, a3;
    {
        float4 q0 = __ldg(w0 + lane), q1 = __ldg(w1 + lane),
               q2 = __ldg(w2 + lane), q3 = __ldg(w3 + lane);
        a0 = q0.x * h0.x + q0.y * h0.y + q0.z * h0.z + q0.w * h0.w;
        a1 = q1.x * h0.x + q1.y * h0.y + q1.z * h0.z + q1.w * h0.w;
        a2 = q2.x * h0.x + q2.y * h0.y + q2.z * h0.z + q2.w * h0.w;
        a3 = q3.x * h0.x + q3.y * h0.y + q3.z * h0.z + q3.w * h0.w;
    }
    {
        float4 q0 = __ldg(w0 + 32 + lane), q1 = __ldg(w1 + 32 + lane),
               q2 = __ldg(w2 + 32 + lane), q3 = __ldg(w3 + 32 + lane);
        a0 += q0.x * h1.x + q0.y * h1.y + q0.z * h1.z + q0.w * h1.w;
        a1 += q1.x * h1.x + q1.y * h1.y + q1.z * h1.z + q1.w * h1.w;
        a2 += q2.x * h1.x + q2.y * h1.y + q2.z * h1.z + q2.w * h1.w;
        a3 += q3.x * h1.x + q3.y * h1.y + q3.z * h1.z + q3.w * h1.w;
    }
#pragma unroll
    for (int o = 16; o; o >>= 1) {
        a0 += __shfl_xor_sync(0xffffffffu, a0, o);
        a1 += __shfl_xor_sync(0xffffffffu, a1, o);
        a2 += __shfl_xor_sync(0xffffffffu, a2, o);
        a3 += __shfl_xor_sync(0xffffffffu, a3, o);
    }
    return make_float4(a0, a1, a2, a3);
}

__global__ void __launch_bounds__(NT, 1) vae_kernel(
    const float* __restrict__ embed, const float* __restrict__ Wpar, const float* __restrict__ bpar,
    const float* __restrict__ Wmu,   const float* __restrict__ bmu,
    const float* __restrict__ Wlv,   const float* __restrict__ blv,
    const float* __restrict__ W1,    const float* __restrict__ b1,
    const float* __restrict__ W2,    const float* __restrict__ b2,
    const float* __restrict__ Wl,    const float* __restrict__ bl,
    const float* __restrict__ Wp,    const float* __restrict__ bp,
    const float* __restrict__ eps,   const int* __restrict__ values,
    float* __restrict__ out, int n_out)
{
    const int tid  = threadIdx.x;
    const int lane = tid & 31;
    const int warp = tid >> 5;
    const int cta  = blockIdx.x;

    __shared__ float4 sh4[192];            // one node's cat vector (3 KB)
    __shared__ float s_stack[MAXLEN * LATENT];  // decoder stack in SMEM (32 KB)
    __shared__ float s_mu[LATENT], s_lv[LATENT];
    __shared__ float s_hm[HIDDEN];
    __shared__ float s_node[LATENT];
    __shared__ float s_co[HIDDEN];
    __shared__ int   sh_flag, sh_op;
    __shared__ unsigned s_epoch;

    // per-launch epoch: launches are stream-serialized, so the 148 tickets of
    // one launch share the same quotient.
    if (tid == 0) s_epoch = (atomicAdd(&g_ticket, 1u) / NB) + 1u;
    __syncthreads();
    const unsigned epoch = s_epoch;

    if (cta >= 128) {
        // ===== ZEROERS (CTAs 128..147): zero out eagerly, hidden under encoder =====
        float4 z4 = make_float4(0.f, 0.f, 0.f, 0.f);
        float4* o4 = reinterpret_cast<float4*>(out);
        int n4 = n_out >> 2;
        for (int i = (cta - 128) * NT + tid; i < n4; i += NZ * NT) o4[i] = z4;
        if (cta == 128) for (int i = (n4 << 2) + tid; i < n_out; i += NT) out[i] = 0.f;
        __syncthreads();
        if (tid == 0) st_rel(&g_zf[cta - 128], epoch);
    } else {
        // ===== ENCODER: split-node dataflow, levels 7..0 =====
        for (int L = 7; L >= 0; --L) {
            const int S = c_S[L];
            if (cta >= (1 << L) * S) break;         // done with encoder duty
            const int node = (1 << L) - 1 + cta / S;
            const int part = cta - (cta / S) * S;
            const int c1n = 2 * node + 1, c2n = 2 * node + 2;
            const bool leaves = (L == 7);

            // parent's own embed row is independent of children: load it first
            float4 v_emb;
            if (tid < 64)
                v_emb = __ldg(reinterpret_cast<const float4*>(embed + (size_t)values[node] * HIDDEN) + tid);

            if (!leaves) {                          // wait for all parts of both children
                const int Sc = c_S[L + 1];
                if (tid < Sc)                    while (ld_acq(&g_pf[c1n * 8 + tid]) != epoch) { }
                if (tid >= 32 && tid < 32 + Sc)  while (ld_acq(&g_pf[c2n * 8 + (tid - 32)]) != epoch) { }
                __syncthreads();
            }

            // gather cat = [emb(values[node]); h(c1); h(c2)] into shared
            if (tid < 192) {
                float4 v;
                if (tid < 64) {
                    v = v_emb;
                } else if (tid < 128) {
                    v = leaves
                      ? __ldg (reinterpret_cast<const float4*>(embed + (size_t)values[c1n] * HIDDEN) + (tid - 64))
                      : __ldcg(reinterpret_cast<const float4*>(g_h + (size_t)c1n * HIDDEN) + (tid - 64));
                } else {
                    v = leaves
                      ? __ldg (reinterpret_cast<const float4*>(embed + (size_t)values[c2n] * HIDDEN) + (tid - 128))
                      : __ldcg(reinterpret_cast<const float4*>(g_h + (size_t)c2n * HIDDEN) + (tid - 128));
                }
                sh4[tid] = v;
            }
            __syncthreads();

            // this part computes row-groups [part*gpp, (part+1)*gpp) of 64
            const int gpp = 64 / S;
            for (int g2 = warp; g2 < gpp; g2 += NWARP) {
                const int grp = part * gpp + g2;
                const float4* w0 = reinterpret_cast<const float4*>(Wpar + (size_t)(4 * grp + 0) * 768);
                const float4* w1 = reinterpret_cast<const float4*>(Wpar + (size_t)(4 * grp + 1) * 768);
                const float4* w2 = reinterpret_cast<const float4*>(Wpar + (size_t)(4 * grp + 2) * 768);
                const float4* w3 = reinterpret_cast<const float4*>(Wpar + (size_t)(4 * grp + 3) * 768);
                float a0 = 0.f, a1 = 0.f, a2 = 0.f, a3 = 0.f;
#pragma unroll
                for (int j = 0; j < 6; ++j) {
                    float4 x  = sh4[j * 32 + lane];
                    float4 q0 = __ldg(w0 + j * 32 + lane);
                    float4 q1 = __ldg(w1 + j * 32 + lane);
                    float4 q2 = __ldg(w2 + j * 32 + lane);
                    float4 q3 = __ldg(w3 + j * 32 + lane);
                    a0 += q0.x * x.x + q0.y * x.y + q0.z * x.z + q0.w * x.w;
                    a1 += q1.x * x.x + q1.y * x.y + q1.z * x.z + q1.w * x.w;
                    a2 += q2.x * x.x + q2.y * x.y + q2.z * x.z + q2.w * x.w;
                    a3 += q3.x * x.x + q3.y * x.y + q3.z * x.z + q3.w * x.w;
                }
#pragma unroll
                for (int o = 16; o; o >>= 1) {
                    a0 += __shfl_xor_sync(0xffffffffu, a0, o);
                    a1 += __shfl_xor_sync(0xffffffffu, a1, o);
                    a2 += __shfl_xor_sync(0xffffffffu, a2, o);
                    a3 += __shfl_xor_sync(0xffffffffu, a3, o);
                }
                if (lane == 0) {
                    float4 bb = __ldg(reinterpret_cast<const float4*>(bpar + 4 * grp));
                    reinterpret_cast<float4*>(g_h + (size_t)node * HIDDEN)[grp] =
                        make_float4(a0 + bb.x, a1 + bb.y, a2 + bb.z, a3 + bb.w);
                }
            }
            __syncthreads();                        // all parts' stores issued
            if (tid == 0) st_rel(&g_pf[node * 8 + part], epoch);
        }
    }

    if (cta != 0) {
        // ===== CONSUMERS (CTAs 1..147) =====
        // out buffer must be fully zeroed before first logits write
        if (tid < NZ) while (ld_acq(&g_zf[tid]) != epoch) { }
        __syncthreads();

        for (int s = 0; ; ++s) {
            if (tid == 0) {                        // single poller per CTA
                while (ld_acq(&g_dtag[s]) != epoch) { }
                sh_flag = g_dflag[s];
                sh_op   = g_dop[s];
            }
            __syncthreads();
            const int flag = sh_flag;
            if (flag < 0) break;
            const int op = sh_op;

            const float4* cb = reinterpret_cast<const float4*>(g_dco[s]);
            const float4 c0 = __ldcg(cb + lane);
            const float4 c1 = __ldcg(cb + 32 + lane);

            const float* W    = flag ? Wp : Wl;
            const float* bias = flag ? bp : bl;
            float* orow = out + (size_t)op * VOCAB;
            const int gw     = (cta - 1) * NWARP + warp;
            const int stride = NCONS * NWARP * 4;
            for (int r = gw * 4; r < VOCAB; r += stride) {
                float s0 = wdot256c(W + (size_t)(r + 0) * HIDDEN, c0, c1, lane);
                float s1 = wdot256c(W + (size_t)(r + 1) * HIDDEN, c0, c1, lane);
                float s2 = wdot256c(W + (size_t)(r + 2) * HIDDEN, c0, c1, lane);
                float s3 = wdot256c(W + (size_t)(r + 3) * HIDDEN, c0, c1, lane);
                if (lane == 0) {
                    orow[r + 0] = s0 + bias[r + 0];
                    orow[r + 1] = s1 + bias[r + 1];
                    orow[r + 2] = s2 + bias[r + 2];
                    orow[r + 3] = s3 + bias[r + 3];
                }
            }
            __syncthreads();                   // keep sh_flag/sh_op stable
        }
        return;
    }

    // ================= CTA 0: latent + sequential decoder =================
    if (tid < 8) while (ld_acq(&g_pf[tid]) != epoch) { }   // all 8 root parts
    __syncthreads();

    {   // mu / logvar from root, 4-row ILP
        const float4* rb = reinterpret_cast<const float4*>(g_h);
        float4 r0c = __ldcg(rb + lane);
        float4 r1c = __ldcg(rb + 32 + lane);
        for (int g = warp; g < 64; g += NWARP) {
            int r0 = 4 * g;
            const float* W    = (r0 < LATENT) ? Wmu : Wlv;
            const float* bb   = (r0 < LATENT) ? bmu : blv;
            int rr = (r0 < LATENT) ? r0 : r0 - LATENT;
            float4 a = wdot256x4(W, rr, r0c, r1c, lane);
            if (lane == 0) {
                float4 b4 = __ldg(reinterpret_cast<const float4*>(bb + rr));
                float* dst = (r0 < LATENT) ? (s_mu + rr) : (s_lv + rr);
                dst[0] = a.x + b4.x; dst[1] = a.y + b4.y;
                dst[2] = a.z + b4.z; dst[3] = a.w + b4.w;
            }
        }
    }
    // zeroers must be done before writing the mu/logvar tail (long since true)
    if (tid < NZ) while (ld_acq(&g_zf[tid]) != epoch) { }
    __syncthreads();
    if (tid < LATENT) {
        float m = s_mu[tid], lv = s_lv[tid];
        out[(size_t)MAXSTEPS * VOCAB + tid]          = m;
        out[(size_t)MAXSTEPS * VOCAB + LATENT + tid] = lv;
        float z = m + eps[tid] * __expf(0.5f * lv);
        s_node[tid] = z;
        s_stack[tid] = z;
    }
    __syncthreads();

    int sp = 1, op = 0, it = 0;
    while (true) {
        // ---- phase A: hmid = leaky(W1@node + b1); co/flag = W2@hmid + b2 ----
        {
            float4 zc = reinterpret_cast<const float4*>(s_node)[lane];
            for (int g = warp; g < 64; g += NWARP) {
                int r0 = 4 * g;
                const float4* w0 = reinterpret_cast<const float4*>(W1 + (size_t)(r0 + 0) * LATENT);
                const float4* w1 = reinterpret_cast<const float4*>(W1 + (size_t)(r0 + 1) * LATENT);
                const float4* w2 = reinterpret_cast<const float4*>(W1 + (size_t)(r0 + 2) * LATENT);
                const float4* w3 = reinterpret_cast<const float4*>(W1 + (size_t)(r0 + 3) * LATENT);
                float4 q0 = __ldg(w0 + lane), q1 = __ldg(w1 + lane),
                       q2 = __ldg(w2 + lane), q3 = __ldg(w3 + lane);
                float a0 = q0.x * zc.x + q0.y * zc.y + q0.z * zc.z + q0.w * zc.w;
                float a1 = q1.x * zc.x + q1.y * zc.y + q1.z * zc.z + q1.w * zc.w;
                float a2 = q2.x * zc.x + q2.y * zc.y + q2.z * zc.z + q2.w * zc.w;
                float a3 = q3.x * zc.x + q3.y * zc.y + q3.z * zc.z + q3.w * zc.w;
#pragma unroll
                for (int o = 16; o; o >>= 1) {
                    a0 += __shfl_xor_sync(0xffffffffu, a0, o);
                    a1 += __shfl_xor_sync(0xffffffffu, a1, o);
                    a2 += __shfl_xor_sync(0xffffffffu, a2, o);
                    a3 += __shfl_xor_sync(0xffffffffu, a3, o);
                }
                if (lane == 0) {
                    float4 b4 = __ldg(reinterpret_cast<const float4*>(b1 + r0));
                    float v0 = a0 + b4.x, v1 = a1 + b4.y, v2 = a2 + b4.z, v3 = a3 + b4.w;
                    s_hm[r0 + 0] = v0 > 0.f ? v0 : 0.2f * v0;
                    s_hm[r0 + 1] = v1 > 0.f ? v1 : 0.2f * v1;
                    s_hm[r0 + 2] = v2 > 0.f ? v2 : 0.2f * v2;
                    s_hm[r0 + 3] = v3 > 0.f ? v3 : 0.2f * v3;
                }
            }
            __syncthreads();
            float4 h0 = reinterpret_cast<const float4*>(s_hm)[lane];
            float4 h1 = reinterpret_cast<const float4*>(s_hm)[32 + lane];
            for (int g = warp; g < 64; g += NWARP) {
                int r0 = 4 * g;
                float4 a = wdot256x4(W2, r0, h0, h1, lane);
                if (lane == 0) {
                    float4 b4 = __ldg(reinterpret_cast<const float4*>(b2 + r0));
                    float v0 = a.x + b4.x;
                    if (r0 == 0) sh_flag = (v0 > 0.f && sp <= MAXLEN - 1) ? 1 : 0;
                    else         s_co[r0 - 1] = v0;
                    s_co[r0 + 0] = a.y + b4.y;
                    s_co[r0 + 1] = a.z + b4.z;
                    s_co[r0 + 2] = a.w + b4.w;
                }
            }
            if (warp == 7) {   // row 256
                const float4* wr = reinterpret_cast<const float4*>(W2 + (size_t)256 * HIDDEN);
                float4 qa = __ldg(wr + lane), qb = __ldg(wr + 32 + lane);
                float s = qa.x * h0.x + qa.y * h0.y + qa.z * h0.z + qa.w * h0.w
                        + qb.x * h1.x + qb.y * h1.y + qb.z * h1.z + qb.w * h1.w;
#pragma unroll
                for (int o = 16; o; o >>= 1) s += __shfl_xor_sync(0xffffffffu, s, o);
                if (lane == 0) s_co[255] = s + __ldg(b2 + 256);
            }
            __syncthreads();
        }
        const int flag = sh_flag;

        // ---- publish step `it` (consumers start logits immediately) ----
        if (tid < 64) reinterpret_cast<float4*>(g_dco[it])[tid] =
                          reinterpret_cast<const float4*>(s_co)[tid];
        if (tid == 0) { g_dflag[it] = flag; g_dop[it] = op; }
        __syncthreads();
        if (tid == 0) st_rel(&g_dtag[it], epoch);

        // ---- next-state compute ----
        int sp_next;
        if (flag) {
            float4 c0 = reinterpret_cast<const float4*>(s_co)[lane];
            float4 c1 = reinterpret_cast<const float4*>(s_co)[32 + lane];
            for (int g = warp; g < 64; g += NWARP) {
                int j0 = 4 * g;
                float4 a = wdot256x4(Wp + (size_t)VOCAB * HIDDEN, j0, c0, c1, lane);
                if (lane == 0) {
                    float4 b4 = __ldg(reinterpret_cast<const float4*>(bp + VOCAB + j0));
                    float v[4] = {a.x + b4.x, a.y + b4.y, a.z + b4.z, a.w + b4.w};
#pragma unroll
                    for (int i = 0; i < 4; ++i) {
                        int j = j0 + i;
                        if (j < LATENT) {
                            s_stack[(sp - 1) * LATENT + j] = v[i];      // ll
                        } else {
                            s_stack[sp * LATENT + (j - LATENT)] = v[i]; // rl
                            s_node[j - LATENT] = v[i];                  // next node = rl
                        }
                    }
                }
            }
            sp_next = sp + 1;
        } else {
            sp_next = sp - 1;
            if (tid < LATENT && sp_next > 0) s_node[tid] = s_stack[(sp_next - 1) * LATENT + tid];
        }
        __syncthreads();

        ++op; ++it;
        if (sp_next <= 0 || it >= MAXSTEPS) {   // publish sentinel
            if (tid == 0) {
                g_dflag[it] = -1;
                g_dop[it]   = op;
                st_rel(&g_dtag[it], epoch);
            }
            break;
        }
        sp = sp_next;
    }
}

extern "C" void kernel_launch(void* const* d_in, const int* in_sizes, int n_in,
                              void* d_out, int out_size) {
    const float* embed = (const float*)d_in[0];
    const float* Wpar  = (const float*)d_in[1];
    const float* bpar  = (const float*)d_in[2];
    const float* Wmu   = (const float*)d_in[3];
    const float* bmu   = (const float*)d_in[4];
    const float* Wlv   = (const float*)d_in[5];
    const float* blv   = (const float*)d_in[6];
    const float* W1    = (const float*)d_in[7];
    const float* b1    = (const float*)d_in[8];
    const float* W2    = (const float*)d_in[9];
    const float* b2    = (const float*)d_in[10];
    const float* Wl    = (const float*)d_in[11];
    const float* bl    = (const float*)d_in[12];
    const float* Wp    = (const float*)d_in[13];
    const float* bp    = (const float*)d_in[14];
    const float* eps   = (const float*)d_in[15];
    const int*   values= (const int*)  d_in[16];
    // d_in[17]=left, d_in[18]=right: fixed complete-tree topology; unused.

    vae_kernel<<<NB, NT>>>(embed, Wpar, bpar, Wmu, bmu, Wlv, blv,
                           W1, b1, W2, b2, Wl, bl, Wp, bp, eps, values,
                           (float*)d_out, out_size);
}

// round 9
// speedup vs baseline: 6.8202x; 1.0804x over previous
#include <cuda_runtime.h>

#define HIDDEN   256
#define LATENT   128
#define VOCAB    32000
#define MAXLEN   64
#define MAXSTEPS 128
#define NB       148
#define NT       256
#define NWARP    (NT/32)
#define NCONS    (NB - 1)          // 147 consumer CTAs
#define NZ       20                // zeroer CTAs: 128..147

// ---------------- device scratch (no allocation allowed) ----------------
__device__ __align__(16) float g_h[255 * HIDDEN];           // encoder hidden states
__device__ __align__(16) float g_dco[MAXSTEPS + 1][HIDDEN]; // published co deck
__device__ int g_dflag[MAXSTEPS + 1];                       // step flag; -1 = sentinel
__device__ int g_dop[MAXSTEPS + 1];                         // step output row
__device__ unsigned g_bf[8][128];                           // (level, block*8+part) flags
__device__ unsigned g_dtag[MAXSTEPS + 1];                   // deck slot tags, epoch-tagged
__device__ unsigned g_zf[NZ];                               // zeroer flags, epoch-tagged
__device__ unsigned g_ticket = 0;                           // monotonic launch ticket

// ---- scoped acquire/release ----
__device__ __forceinline__ void st_rel(unsigned* p, unsigned v) {
    asm volatile("st.release.gpu.u32 [%0], %1;" :: "l"(p), "r"(v) : "memory");
}
__device__ __forceinline__ unsigned ld_acq(const unsigned* p) {
    unsigned v;
    asm volatile("ld.acquire.gpu.u32 %0, [%1];" : "=r"(v) : "l"(p) : "memory");
    return v;
}

// warp dot: 256-float row vs lane-resident x, streaming (L2)
__device__ __forceinline__ float wdot256c(const float* __restrict__ row,
                                          float4 c0, float4 c1, int lane) {
    const float4* r4 = reinterpret_cast<const float4*>(row);
    float4 a = __ldcg(r4 + lane);
    float4 b = __ldcg(r4 + 32 + lane);
    float s = a.x * c0.x + a.y * c0.y + a.z * c0.z + a.w * c0.w;
    s      += b.x * c1.x + b.y * c1.y + b.z * c1.z + b.w * c1.w;
#pragma unroll
    for (int o = 16; o; o >>= 1) s += __shfl_xor_sync(0xffffffffu, s, o);
    return s;
}

// 4 interleaved 256-wide dots (rows r0..r0+3 of W), L1-cached
__device__ __forceinline__ float4 wdot256x4(const float* __restrict__ W, int r0,
                                            float4 h0, float4 h1, int lane) {
    const float4* w0 = reinterpret_cast<const float4*>(W + (size_t)(r0 + 0) * HIDDEN);
    const float4* w1 = reinterpret_cast<const float4*>(W + (size_t)(r0 + 1) * HIDDEN);
    const float4* w2 = reinterpret_cast<const float4*>(W + (size_t)(r0 + 2) * HIDDEN);
    const float4* w3 = reinterpret_cast<const float4*>(W + (size_t)(r0 + 3) * HIDDEN);
    float a0, a1, a2, a3;
    {
        float4 q0 = __ldg(w0 + lane), q1 = __ldg(w1 + lane),
               q2 = __ldg(w2 + lane), q3 = __ldg(w3 + lane);
        a0 = q0.x * h0.x + q0.y * h0.y + q0.z * h0.z + q0.w * h0.w;
        a1 = q1.x * h0.x + q1.y * h0.y + q1.z * h0.z + q1.w * h0.w;
        a2 = q2.x * h0.x + q2.y * h0.y + q2.z * h0.z + q2.w * h0.w;
        a3 = q3.x * h0.x + q3.y * h0.y + q3.z * h0.z + q3.w * h0.w;
    }
    {
        float4 q0 = __ldg(w0 + 32 + lane), q1 = __ldg(w1 + 32 + lane),
               q2 = __ldg(w2 + 32 + lane), q3 = __ldg(w3 + 32 + lane);
        a0 += q0.x * h1.x + q0.y * h1.y + q0.z * h1.z + q0.w * h1.w;
        a1 += q1.x * h1.x + q1.y * h1.y + q1.z * h1.z + q1.w * h1.w;
        a2 += q2.x * h1.x + q2.y * h1.y + q2.z * h1.z + q2.w * h1.w;
        a3 += q3.x * h1.x + q3.y * h1.y + q3.z * h1.z + q3.w * h1.w;
    }
#pragma unroll
    for (int o = 16; o; o >>= 1) {
        a0 += __shfl_xor_sync(0xffffffffu, a0, o);
        a1 += __shfl_xor_sync(0xffffffffu, a1, o);
        a2 += __shfl_xor_sync(0xffffffffu, a2, o);
        a3 += __shfl_xor_sync(0xffffffffu, a3, o);
    }
    return make_float4(a0, a1, a2, a3);
}

// butterfly: reduce 32 per-lane accumulators across 32 lanes; lane L ends with acc[L]'s total
#define BSTEP(o) { bool up = (lane & (o)) != 0; \
    _Pragma("unroll") for (int i = 0; i < (o); ++i) { \
        float s_ = up ? acc[i] : acc[i + (o)]; \
        float r_ = __shfl_xor_sync(0xffffffffu, s_, (o)); \
        acc[i] = (up ? acc[i + (o)] : acc[i]) + r_; } }

// ===== batched encoder level: block of 8 nodes, this CTA = (blk, part) =====
__device__ __forceinline__ void enc_batched(
    const float* __restrict__ embed, const float* __restrict__ Wpar,
    const float* __restrict__ bpar,  const int* __restrict__ values,
    float4* sh4, int lvl, int base, int blk, int part, unsigned epoch,
    int tid, int lane, int warp)
{
    const int n0 = base + blk * 8;
    const bool leaves = (lvl == 7);
    if (!leaves) {   // wait: child level's 2 blocks x 8 parts = 16 flags
        if (tid < 16) while (ld_acq(&g_bf[lvl + 1][blk * 16 + tid]) != epoch) { }
        __syncthreads();
    }
    // gather cat rows for 8 nodes: [emb(n); h(2n+1); h(2n+2)] (children contiguous)
    const int c0 = 2 * n0 + 1;
    for (int idx = tid; idx < 8 * 192; idx += NT) {
        int m = idx / 192, k4 = idx - m * 192;
        float4 v;
        if (k4 < 64) {
            v = __ldg(reinterpret_cast<const float4*>(embed) + (size_t)values[n0 + m] * 64 + k4);
        } else {
            int cg = c0 + 2 * m + ((k4 >> 6) - 1);
            int off = k4 & 63;
            v = leaves
              ? __ldg (reinterpret_cast<const float4*>(embed) + (size_t)values[cg] * 64 + off)
              : __ldcg(reinterpret_cast<const float4*>(g_h) + (size_t)cg * 64 + off);
        }
        sh4[idx] = v;
    }
    __syncthreads();
    // matvec: warp computes 4 rows x 8 nodes, register accumulators
    {
        const int grp = (part << 3) + warp;     // 0..63
        const int r0 = grp << 2;
        const float* wr = Wpar + (size_t)r0 * 768;
        const float4* w0 = reinterpret_cast<const float4*>(wr);
        const float4* w1 = reinterpret_cast<const float4*>(wr + 768);
        const float4* w2 = reinterpret_cast<const float4*>(wr + 1536);
        const float4* w3 = reinterpret_cast<const float4*>(wr + 2304);
        float acc[32];
#pragma unroll
        for (int i = 0; i < 32; ++i) acc[i] = 0.f;
#pragma unroll
        for (int j = 0; j < 6; ++j) {
            const int o = j * 32 + lane;
            float4 q0 = __ldg(w0 + o), q1 = __ldg(w1 + o),
                   q2 = __ldg(w2 + o), q3 = __ldg(w3 + o);
#pragma unroll
            for (int m = 0; m < 8; ++m) {
                float4 x = sh4[m * 192 + o];
                acc[m]      += q0.x * x.x + q0.y * x.y + q0.z * x.z + q0.w * x.w;
                acc[8 + m]  += q1.x * x.x + q1.y * x.y + q1.z * x.z + q1.w * x.w;
                acc[16 + m] += q2.x * x.x + q2.y * x.y + q2.z * x.z + q2.w * x.w;
                acc[24 + m] += q3.x * x.x + q3.y * x.y + q3.z * x.z + q3.w * x.w;
            }
        }
        BSTEP(16) BSTEP(8) BSTEP(4) BSTEP(2) BSTEP(1)
        // lane L holds sum for row=(L>>3), node=(L&7)
        float bb = __ldg(bpar + r0 + (lane >> 3));
        g_h[(size_t)(n0 + (lane & 7)) * HIDDEN + r0 + (lane >> 3)] = acc[0] + bb;
    }
    __syncthreads();
    if (tid == 0) st_rel(&g_bf[lvl][blk * 8 + part], epoch);
}

// ===== split encoder level: single node, this CTA = (node, part) =====
__device__ __forceinline__ void enc_split(
    const float* __restrict__ embed, const float* __restrict__ Wpar,
    const float* __restrict__ bpar,  const int* __restrict__ values,
    float4* sh4, int lvl, int node, int ln, int part, unsigned epoch,
    int tid, int lane, int warp)
{
    if (lvl == 3) {   // children live in one batched L4 block (8 flags)
        if (tid < 8) while (ld_acq(&g_bf[4][((ln >> 2) << 3) + tid]) != epoch) { }
    } else {          // children = 2 split nodes x 8 parts = 16 flags
        if (tid < 16) while (ld_acq(&g_bf[lvl + 1][(ln << 4) + tid]) != epoch) { }
    }
    __syncthreads();
    if (tid < 192) {
        float4 v;
        if (tid < 64) {
            v = __ldg(reinterpret_cast<const float4*>(embed) + (size_t)values[node] * 64 + tid);
        } else {
            int cg = 2 * node + 1 + ((tid >> 6) - 1);
            v = __ldcg(reinterpret_cast<const float4*>(g_h) + (size_t)cg * 64 + (tid & 63));
        }
        sh4[tid] = v;
    }
    __syncthreads();
    {
        const int grp = (part << 3) + warp;
        const int r0 = grp << 2;
        const float* wr = Wpar + (size_t)r0 * 768;
        const float4* w0 = reinterpret_cast<const float4*>(wr);
        const float4* w1 = reinterpret_cast<const float4*>(wr + 768);
        const float4* w2 = reinterpret_cast<const float4*>(wr + 1536);
        const float4* w3 = reinterpret_cast<const float4*>(wr + 2304);
        float a0 = 0.f, a1 = 0.f, a2 = 0.f, a3 = 0.f;
#pragma unroll
        for (int j = 0; j < 6; ++j) {
            const int o = j * 32 + lane;
            float4 x  = sh4[o];
            float4 q0 = __ldg(w0 + o), q1 = __ldg(w1 + o),
                   q2 = __ldg(w2 + o), q3 = __ldg(w3 + o);
            a0 += q0.x * x.x + q0.y * x.y + q0.z * x.z + q0.w * x.w;
            a1 += q1.x * x.x + q1.y * x.y + q1.z * x.z + q1.w * x.w;
            a2 += q2.x * x.x + q2.y * x.y + q2.z * x.z + q2.w * x.w;
            a3 += q3.x * x.x + q3.y * x.y + q3.z * x.z + q3.w * x.w;
        }
#pragma unroll
        for (int o = 16; o; o >>= 1) {
            a0 += __shfl_xor_sync(0xffffffffu, a0, o);
            a1 += __shfl_xor_sync(0xffffffffu, a1, o);
            a2 += __shfl_xor_sync(0xffffffffu, a2, o);
            a3 += __shfl_xor_sync(0xffffffffu, a3, o);
        }
        if (lane == 0) {
            float4 bb = __ldg(reinterpret_cast<const float4*>(bpar + r0));
            reinterpret_cast<float4*>(g_h + (size_t)node * HIDDEN)[grp] =
                make_float4(a0 + bb.x, a1 + bb.y, a2 + bb.z, a3 + bb.w);
        }
    }
    __syncthreads();
    if (tid == 0) st_rel(&g_bf[lvl][(ln << 3) + part], epoch);
}

// ===== L2 prefetch with warp-uniform bail on step-0 publish =====
__device__ __forceinline__ void prefetch_l2(const float* W, size_t bytes, int nct, int idx,
                                            unsigned epoch, int tid, int lane) {
    const char* base = reinterpret_cast<const char*>(W);
    size_t off = ((size_t)idx * NT + tid) * 128;
    const size_t step = (size_t)nct * NT * 128;
    int k = 0;
    while (off < bytes) {
        asm volatile("prefetch.global.L2 [%0];" :: "l"(base + off));
        off += step;
        if ((++k & 7) == 0) {
            unsigned d = 0;
            if (lane == 0) d = *(volatile unsigned*)&g_dtag[0];
            d = __shfl_sync(0xffffffffu, d, 0);
            if (d == epoch) return;
        }
    }
}

__global__ void __launch_bounds__(NT, 1) vae_kernel(
    const float* __restrict__ embed, const float* __restrict__ Wpar, const float* __restrict__ bpar,
    const float* __restrict__ Wmu,   const float* __restrict__ bmu,
    const float* __restrict__ Wlv,   const float* __restrict__ blv,
    const float* __restrict__ W1,    const float* __restrict__ b1,
    const float* __restrict__ W2,    const float* __restrict__ b2,
    const float* __restrict__ Wl,    const float* __restrict__ bl,
    const float* __restrict__ Wp,    const float* __restrict__ bp,
    const float* __restrict__ eps,   const int* __restrict__ values,
    float* __restrict__ out, int n_out)
{
    const int tid  = threadIdx.x;
    const int lane = tid & 31;
    const int warp = tid >> 5;
    const int cta  = blockIdx.x;

    __shared__ float4 sh4[8 * 192];             // 24 KB cat buffers
    __shared__ float s_stack[MAXLEN * LATENT];  // decoder stack (32 KB, CTA 0)
    __shared__ float s_mu[LATENT], s_lv[LATENT];
    __shared__ float s_hm[HIDDEN];
    __shared__ float s_node[LATENT];
    __shared__ float s_co[HIDDEN];
    __shared__ int   sh_flag, sh_op;
    __shared__ unsigned s_epoch;

    if (tid == 0) s_epoch = (atomicAdd(&g_ticket, 1u) / NB) + 1u;
    __syncthreads();
    const unsigned epoch = s_epoch;

    if (cta >= 128) {
        // ===== ZEROERS (CTAs 128..147) =====
        float4 z4 = make_float4(0.f, 0.f, 0.f, 0.f);
        float4* o4 = reinterpret_cast<float4*>(out);
        int n4 = n_out >> 2;
        for (int i = (cta - 128) * NT + tid; i < n4; i += NZ * NT) o4[i] = z4;
        if (cta == 128) for (int i = (n4 << 2) + tid; i < n_out; i += NT) out[i] = 0.f;
        __syncthreads();
        if (tid == 0) st_rel(&g_zf[cta - 128], epoch);
    } else {
        // ===== ENCODER =====
        enc_batched(embed, Wpar, bpar, values, sh4, 7, 127, cta >> 3, cta & 7, epoch, tid, lane, warp);
        if (cta < 64) enc_batched(embed, Wpar, bpar, values, sh4, 6, 63, cta >> 3, cta & 7, epoch, tid, lane, warp);
        if (cta < 32) enc_batched(embed, Wpar, bpar, values, sh4, 5, 31, cta >> 3, cta & 7, epoch, tid, lane, warp);
        if (cta < 16) enc_batched(embed, Wpar, bpar, values, sh4, 4, 15, cta >> 3, cta & 7, epoch, tid, lane, warp);
        if (cta < 64) enc_split(embed, Wpar, bpar, values, sh4, 3, 7 + (cta >> 3), cta >> 3, cta & 7, epoch, tid, lane, warp);
        if (cta < 32) enc_split(embed, Wpar, bpar, values, sh4, 2, 3 + (cta >> 3), cta >> 3, cta & 7, epoch, tid, lane, warp);
        if (cta < 16) enc_split(embed, Wpar, bpar, values, sh4, 1, 1 + (cta >> 3), cta >> 3, cta & 7, epoch, tid, lane, warp);
        if (cta <  8) enc_split(embed, Wpar, bpar, values, sh4, 0, 0, 0, cta & 7, epoch, tid, lane, warp);
    }

    if (cta != 0) {
        // ===== PREFETCH (early-free CTAs 64..147): warm Wl/Wp into L2 =====
        if (cta >= 64) {
            int id = cta - 64;
            if (id < 28) prefetch_l2(Wl, (size_t)VOCAB * HIDDEN * 4, 28, id, epoch, tid, lane);
            else         prefetch_l2(Wp, (size_t)(VOCAB + 2 * LATENT) * HIDDEN * 4, 56, id - 28, epoch, tid, lane);
        }

        // ===== CONSUMERS (CTAs 1..147) =====
        if (tid < NZ) while (ld_acq(&g_zf[tid]) != epoch) { }
        __syncthreads();

        for (int s = 0; ; ++s) {
            if (tid == 0) {
                while (ld_acq(&g_dtag[s]) != epoch) { }
                sh_flag = g_dflag[s];
                sh_op   = g_dop[s];
            }
            __syncthreads();
            const int flag = sh_flag;
            if (flag < 0) break;
            const int op = sh_op;

            const float4* cb = reinterpret_cast<const float4*>(g_dco[s]);
            const float4 c0 = __ldcg(cb + lane);
            const float4 c1 = __ldcg(cb + 32 + lane);

            const float* W    = flag ? Wp : Wl;
            const float* bias = flag ? bp : bl;
            float* orow = out + (size_t)op * VOCAB;
            const int gw     = (cta - 1) * NWARP + warp;
            const int stride = NCONS * NWARP * 4;
            for (int r = gw * 4; r < VOCAB; r += stride) {
                float s0 = wdot256c(W + (size_t)(r + 0) * HIDDEN, c0, c1, lane);
                float s1 = wdot256c(W + (size_t)(r + 1) * HIDDEN, c0, c1, lane);
                float s2 = wdot256c(W + (size_t)(r + 2) * HIDDEN, c0, c1, lane);
                float s3 = wdot256c(W + (size_t)(r + 3) * HIDDEN, c0, c1, lane);
                if (lane == 0) {
                    orow[r + 0] = s0 + bias[r + 0];
                    orow[r + 1] = s1 + bias[r + 1];
                    orow[r + 2] = s2 + bias[r + 2];
                    orow[r + 3] = s3 + bias[r + 3];
                }
            }
            __syncthreads();
        }
        return;
    }

    // ================= CTA 0: latent + sequential decoder =================
    if (tid < 8) while (ld_acq(&g_bf[0][tid]) != epoch) { }   // root parts
    __syncthreads();

    {   // mu / logvar from root, 4-row ILP
        const float4* rb = reinterpret_cast<const float4*>(g_h);
        float4 r0c = __ldcg(rb + lane);
        float4 r1c = __ldcg(rb + 32 + lane);
        for (int g = warp; g < 64; g += NWARP) {
            int r0 = 4 * g;
            const float* W    = (r0 < LATENT) ? Wmu : Wlv;
            const float* bb   = (r0 < LATENT) ? bmu : blv;
            int rr = (r0 < LATENT) ? r0 : r0 - LATENT;
            float4 a = wdot256x4(W, rr, r0c, r1c, lane);
            if (lane == 0) {
                float4 b4 = __ldg(reinterpret_cast<const float4*>(bb + rr));
                float* dst = (r0 < LATENT) ? (s_mu + rr) : (s_lv + rr);
                dst[0] = a.x + b4.x; dst[1] = a.y + b4.y;
                dst[2] = a.z + b4.z; dst[3] = a.w + b4.w;
            }
        }
    }
    if (tid < NZ) while (ld_acq(&g_zf[tid]) != epoch) { }
    __syncthreads();
    if (tid < LATENT) {
        float m = s_mu[tid], lv = s_lv[tid];
        out[(size_t)MAXSTEPS * VOCAB + tid]          = m;
        out[(size_t)MAXSTEPS * VOCAB + LATENT + tid] = lv;
        float z = m + eps[tid] * __expf(0.5f * lv);
        s_node[tid] = z;
        s_stack[tid] = z;
    }
    __syncthreads();

    int sp = 1, op = 0, it = 0;
    while (true) {
        // ---- phase A: hmid = leaky(W1@node + b1); co/flag = W2@hmid + b2 ----
        {
            float4 zc = reinterpret_cast<const float4*>(s_node)[lane];
            for (int g = warp; g < 64; g += NWARP) {
                int r0 = 4 * g;
                const float4* w0 = reinterpret_cast<const float4*>(W1 + (size_t)(r0 + 0) * LATENT);
                const float4* w1 = reinterpret_cast<const float4*>(W1 + (size_t)(r0 + 1) * LATENT);
                const float4* w2 = reinterpret_cast<const float4*>(W1 + (size_t)(r0 + 2) * LATENT);
                const float4* w3 = reinterpret_cast<const float4*>(W1 + (size_t)(r0 + 3) * LATENT);
                float4 q0 = __ldg(w0 + lane), q1 = __ldg(w1 + lane),
                       q2 = __ldg(w2 + lane), q3 = __ldg(w3 + lane);
                float a0 = q0.x * zc.x + q0.y * zc.y + q0.z * zc.z + q0.w * zc.w;
                float a1 = q1.x * zc.x + q1.y * zc.y + q1.z * zc.z + q1.w * zc.w;
                float a2 = q2.x * zc.x + q2.y * zc.y + q2.z * zc.z + q2.w * zc.w;
                float a3 = q3.x * zc.x + q3.y * zc.y + q3.z * zc.z + q3.w * zc.w;
#pragma unroll
                for (int o = 16; o; o >>= 1) {
                    a0 += __shfl_xor_sync(0xffffffffu, a0, o);
                    a1 += __shfl_xor_sync(0xffffffffu, a1, o);
                    a2 += __shfl_xor_sync(0xffffffffu, a2, o);
                    a3 += __shfl_xor_sync(0xffffffffu, a3, o);
                }
                if (lane == 0) {
                    float4 b4 = __ldg(reinterpret_cast<const float4*>(b1 + r0));
                    float v0 = a0 + b4.x, v1 = a1 + b4.y, v2 = a2 + b4.z, v3 = a3 + b4.w;
                    s_hm[r0 + 0] = v0 > 0.f ? v0 : 0.2f * v0;
                    s_hm[r0 + 1] = v1 > 0.f ? v1 : 0.2f * v1;
                    s_hm[r0 + 2] = v2 > 0.f ? v2 : 0.2f * v2;
                    s_hm[r0 + 3] = v3 > 0.f ? v3 : 0.2f * v3;
                }
            }
            __syncthreads();
            float4 h0 = reinterpret_cast<const float4*>(s_hm)[lane];
            float4 h1 = reinterpret_cast<const float4*>(s_hm)[32 + lane];
            for (int g = warp; g < 64; g += NWARP) {
                int r0 = 4 * g;
                float4 a = wdot256x4(W2, r0, h0, h1, lane);
                if (lane == 0) {
                    float4 b4 = __ldg(reinterpret_cast<const float4*>(b2 + r0));
                    float v0 = a.x + b4.x;
                    if (r0 == 0) sh_flag = (v0 > 0.f && sp <= MAXLEN - 1) ? 1 : 0;
                    else         s_co[r0 - 1] = v0;
                    s_co[r0 + 0] = a.y + b4.y;
                    s_co[r0 + 1] = a.z + b4.z;
                    s_co[r0 + 2] = a.w + b4.w;
                }
            }
            if (warp == 7) {   // row 256
                const float4* wr = reinterpret_cast<const float4*>(W2 + (size_t)256 * HIDDEN);
                float4 qa = __ldg(wr + lane), qb = __ldg(wr + 32 + lane);
                float s = qa.x * h0.x + qa.y * h0.y + qa.z * h0.z + qa.w * h0.w
                        + qb.x * h1.x + qb.y * h1.y + qb.z * h1.z + qb.w * h1.w;
#pragma unroll
                for (int o = 16; o; o >>= 1) s += __shfl_xor_sync(0xffffffffu, s, o);
                if (lane == 0) s_co[255] = s + __ldg(b2 + 256);
            }
            __syncthreads();
        }
        const int flag = sh_flag;

        // ---- publish step `it` ----
        if (tid < 64) reinterpret_cast<float4*>(g_dco[it])[tid] =
                          reinterpret_cast<const float4*>(s_co)[tid];
        if (tid == 0) { g_dflag[it] = flag; g_dop[it] = op; }
        __syncthreads();
        if (tid == 0) st_rel(&g_dtag[it], epoch);

        // ---- next-state compute ----
        int sp_next;
        if (flag) {
            float4 c0 = reinterpret_cast<const float4*>(s_co)[lane];
            float4 c1 = reinterpret_cast<const float4*>(s_co)[32 + lane];
            for (int g = warp; g < 64; g += NWARP) {
                int j0 = 4 * g;
                float4 a = wdot256x4(Wp + (size_t)VOCAB * HIDDEN, j0, c0, c1, lane);
                if (lane == 0) {
                    float4 b4 = __ldg(reinterpret_cast<const float4*>(bp + VOCAB + j0));
                    float v[4] = {a.x + b4.x, a.y + b4.y, a.z + b4.z, a.w + b4.w};
#pragma unroll
                    for (int i = 0; i < 4; ++i) {
                        int j = j0 + i;
                        if (j < LATENT) {
                            s_stack[(sp - 1) * LATENT + j] = v[i];      // ll
                        } else {
                            s_stack[sp * LATENT + (j - LATENT)] = v[i]; // rl
                            s_node[j - LATENT] = v[i];                  // next node = rl
                        }
                    }
                }
            }
            sp_next = sp + 1;
        } else {
            sp_next = sp - 1;
            if (tid < LATENT && sp_next > 0) s_node[tid] = s_stack[(sp_next - 1) * LATENT + tid];
        }
        __syncthreads();

        ++op; ++it;
        if (sp_next <= 0 || it >= MAXSTEPS) {
            if (tid == 0) {
                g_dflag[it] = -1;
                g_dop[it]   = op;
                st_rel(&g_dtag[it], epoch);
            }
            break;
        }
        sp = sp_next;
    }
}

extern "C" void kernel_launch(void* const* d_in, const int* in_sizes, int n_in,
                              void* d_out, int out_size) {
    const float* embed = (const float*)d_in[0];
    const float* Wpar  = (const float*)d_in[1];
    const float* bpar  = (const float*)d_in[2];
    const float* Wmu   = (const float*)d_in[3];
    const float* bmu   = (const float*)d_in[4];
    const float* Wlv   = (const float*)d_in[5];
    const float* blv   = (const float*)d_in[6];
    const float* W1    = (const float*)d_in[7];
    const float* b1    = (const float*)d_in[8];
    const float* W2    = (const float*)d_in[9];
    const float* b2    = (const float*)d_in[10];
    const float* Wl    = (const float*)d_in[11];
    const float* bl    = (const float*)d_in[12];
    const float* Wp    = (const float*)d_in[13];
    const float* bp    = (const float*)d_in[14];
    const float* eps   = (const float*)d_in[15];
    const int*   values= (const int*)  d_in[16];
    // d_in[17]=left, d_in[18]=right: fixed complete-tree topology; unused.

    vae_kernel<<<NB, NT>>>(embed, Wpar, bpar, Wmu, bmu, Wlv, blv,
                           W1, b1, W2, b2, Wl, bl, Wp, bp, eps, values,
                           (float*)d_out, out_size);
}